// round 14
// baseline (speedup 1.0000x reference)
#include <cuda_runtime.h>
#include <cuda_bf16.h>
#include <cstdint>
#include <cstddef>

#define BATCH 8
#define SEQ   2048
#define DIM   768
#define MTOT  (BATCH*SEQ)   // 16384
#define NCH   12            // 768 / 64 k-chunks
#define TILE_BYTES 16384    // one (128-row x 64-k) bf16 tile, SW128-swizzled

// ---------------- scratch (no dynamic allocation allowed) -------------------
__device__ __align__(256) __nv_bfloat16 g_X1b[(size_t)MTOT*DIM];
__device__ __align__(256) __nv_bfloat16 g_X2b[(size_t)MTOT*DIM];
__device__ __align__(256) __nv_bfloat16 g_Q  [(size_t)MTOT*DIM];
__device__ __align__(256) __nv_bfloat16 g_K  [(size_t)MTOT*DIM];
__device__ __align__(256) __nv_bfloat16 g_Wqt[(size_t)DIM*DIM];
__device__ __align__(256) __nv_bfloat16 g_Wkt[(size_t)DIM*DIM];
__device__ float g_num[2][BATCH*SEQ];
__device__ float g_den[2][BATCH*SEQ];

// ---------------- helpers ----------------------------------------------------
#define SWZ(o) ((o) ^ (((o) >> 3) & 0x70))

__device__ __forceinline__ uint32_t smem_u32(const void* p) {
    uint32_t a;
    asm("{ .reg .u64 t; cvta.to.shared.u64 t, %1; cvt.u32.u64 %0, t; }"
        : "=r"(a) : "l"(p));
    return a;
}
__device__ __forceinline__ void ldsm_x4(uint32_t* r, uint32_t addr) {
    asm volatile("ldmatrix.sync.aligned.m8n8.x4.shared.b16 {%0,%1,%2,%3}, [%4];"
                 : "=r"(r[0]), "=r"(r[1]), "=r"(r[2]), "=r"(r[3]) : "r"(addr));
}
__device__ __forceinline__ void mma_bf16(float* c, const uint32_t* a,
                                         uint32_t b0, uint32_t b1) {
    asm volatile(
        "mma.sync.aligned.m16n8k16.row.col.f32.bf16.bf16.f32 "
        "{%0,%1,%2,%3}, {%4,%5,%6,%7}, {%8,%9}, {%0,%1,%2,%3};"
        : "+f"(c[0]), "+f"(c[1]), "+f"(c[2]), "+f"(c[3])
        : "r"(a[0]), "r"(a[1]), "r"(a[2]), "r"(a[3]), "r"(b0), "r"(b1));
}
__device__ __forceinline__ float fast_tanh(float x) {
    float y; asm("tanh.approx.f32 %0, %1;" : "=f"(y) : "f"(x)); return y;
}

// mbarrier + bulk-copy primitives (Hopper+ PTX; valid on plain sm_103)
#define MBARRIER_INIT(addr, cnt) \
    asm volatile("mbarrier.init.shared.b64 [%0], %1;" :: "r"(addr), "r"(cnt) : "memory")
#define MBARRIER_EXPECT_TX(addr, bytes) \
    asm volatile("mbarrier.arrive.expect_tx.shared.b64 _, [%0], %1;" \
                 :: "r"(addr), "r"(bytes) : "memory")
#define MBARRIER_ARRIVE(addr) \
    asm volatile("mbarrier.arrive.release.cta.shared.b64 _, [%0];" \
                 :: "r"(addr) : "memory")
#define MBARRIER_WAIT_PARITY(mbar, par) do { \
    uint32_t _m = (uint32_t)(mbar), _p = (uint32_t)(par), _d; \
    asm volatile("{\n\t.reg .pred p;\n\t" \
        "mbarrier.try_wait.parity.acquire.cta.shared::cta.b64 p, [%1], %2;\n\t" \
        "selp.b32 %0, 1, 0, p;\n\t}" : "=r"(_d) : "r"(_m), "r"(_p) : "memory"); \
    if (!_d) { \
        asm volatile("{\n\t.reg .pred P1;\n\t" \
            "WL_%=:\n\t" \
            "mbarrier.try_wait.parity.acquire.cta.shared::cta.b64 P1, [%0], %1, 0x989680;\n\t" \
            "@P1 bra.uni WD_%=;\n\t" \
            "bra.uni WL_%=;\n\t" \
            "WD_%=:\n\t}" :: "r"(_m), "r"(_p) : "memory"); \
    } \
} while (0)
__device__ __forceinline__ void bulk_g2s(uint32_t dst, const void* src,
                                         uint32_t bytes, uint32_t mbar) {
    asm volatile(
        "cp.async.bulk.shared::cluster.global.mbarrier::complete_tx::bytes "
        "[%0], [%1], %2, [%3];"
        :: "r"(dst), "l"(src), "r"(bytes), "r"(mbar) : "memory");
}

// 128x128x64 chunk MMA (8 warps, 32x64 warp tiles), XOR-folded addressing.
#define CHUNK_MMA_SW(AsX, BsX) do { \
    const uint32_t _Ab0 = (AsX) + aswz0; \
    const uint32_t _Ab1 = (AsX) + aswz1; \
    const uint32_t _Bb  = (BsX) + bswz0; \
    _Pragma("unroll") \
    for (int ks = 0; ks < 4; ks++) { \
        const uint32_t _kx = ks * 32; \
        uint32_t a0[4], a1[4], bmA[4], bmB[4]; \
        ldsm_x4(a0,  _Ab0 ^ _kx); \
        ldsm_x4(a1,  _Ab1 ^ _kx); \
        ldsm_x4(bmA, _Bb ^ _kx); \
        _Pragma("unroll") \
        for (int np = 0; np < 4; np++) { \
            uint32_t* bc = (np & 1) ? bmB : bmA; \
            uint32_t* bn_ = (np & 1) ? bmA : bmB; \
            if (np < 3) \
                ldsm_x4(bn_, (_Bb + (np + 1) * 2048) ^ _kx); \
            mma_bf16(acc[0][np*2],   a0, bc[0], bc[2]); \
            mma_bf16(acc[0][np*2+1], a0, bc[1], bc[3]); \
            mma_bf16(acc[1][np*2],   a1, bc[0], bc[2]); \
            mma_bf16(acc[1][np*2+1], a1, bc[1], bc[3]); \
        } \
    } \
} while (0)

// 128x128x64 chunk MMA for 16 warps (4m x 4n), 32x32 warp tiles.
#define CHUNK_MMA_SW16(AsX, BsX) do { \
    const uint32_t _Ab0 = (AsX) + aswz0; \
    const uint32_t _Ab1 = (AsX) + aswz1; \
    const uint32_t _Bb  = (BsX) + bswz0; \
    _Pragma("unroll") \
    for (int ks = 0; ks < 4; ks++) { \
        const uint32_t _kx = ks * 32; \
        uint32_t a0[4], a1[4], bmA[4], bmB[4]; \
        ldsm_x4(a0,  _Ab0 ^ _kx); \
        ldsm_x4(a1,  _Ab1 ^ _kx); \
        ldsm_x4(bmA, _Bb ^ _kx); \
        ldsm_x4(bmB, (_Bb + 2048) ^ _kx); \
        mma_bf16(acc[0][0], a0, bmA[0], bmA[2]); \
        mma_bf16(acc[0][1], a0, bmA[1], bmA[3]); \
        mma_bf16(acc[1][0], a1, bmA[0], bmA[2]); \
        mma_bf16(acc[1][1], a1, bmA[1], bmA[3]); \
        mma_bf16(acc[0][2], a0, bmB[0], bmB[2]); \
        mma_bf16(acc[0][3], a0, bmB[1], bmB[3]); \
        mma_bf16(acc[1][2], a1, bmB[0], bmB[2]); \
        mma_bf16(acc[1][3], a1, bmB[1], bmB[3]); \
    } \
} while (0)

// ---------------------------------------------------------------------------
// convert: f32 row-major -> bf16 blocked SW128 tiles
// ---------------------------------------------------------------------------
__global__ void convert_bf16_2(const float* __restrict__ x1, const float* __restrict__ x2,
                               __nv_bfloat16* __restrict__ y1, __nv_bfloat16* __restrict__ y2)
{
    const float* x = blockIdx.z ? x2 : x1;
    char* y = (char*)(blockIdx.z ? y2 : y1);
    const size_t i = ((size_t)blockIdx.x * blockDim.x + threadIdx.x) * 8;
    const uint32_t m = (uint32_t)(i / DIM), k = (uint32_t)(i % DIM);
    float4 v0 = *(const float4*)(x + i);
    float4 v1 = *(const float4*)(x + i + 4);
    __nv_bfloat162 a = __floats2bfloat162_rn(v0.x, v0.y);
    __nv_bfloat162 b = __floats2bfloat162_rn(v0.z, v0.w);
    __nv_bfloat162 c = __floats2bfloat162_rn(v1.x, v1.y);
    __nv_bfloat162 d = __floats2bfloat162_rn(v1.z, v1.w);
    uint4 st; st.x = *(uint32_t*)&a; st.y = *(uint32_t*)&b;
    st.z = *(uint32_t*)&c; st.w = *(uint32_t*)&d;
    const size_t tbase = ((size_t)(m >> 7) * NCH + (k >> 6)) << 14;
    *(uint4*)(y + tbase + SWZ((m & 127) * 128 + (k & 63) * 2)) = st;
}

// transpose: W[k][n] f32 -> Wt blocked SW128 tiles over (n-tile, k-chunk)
__global__ void transpose_bf16_2(const float* __restrict__ W1, const float* __restrict__ W2,
                                 __nv_bfloat16* __restrict__ T1, __nv_bfloat16* __restrict__ T2)
{
    const float* W = blockIdx.z ? W2 : W1;
    char* Wt = (char*)(blockIdx.z ? T2 : T1);
    __shared__ float t[32][33];
    int tx = threadIdx.x, ty = threadIdx.y;
    int bk = blockIdx.y * 32, bn = blockIdx.x * 32;
#pragma unroll
    for (int j = 0; j < 4; j++)
        t[ty + j * 8][tx] = W[(size_t)(bk + ty + j * 8) * DIM + bn + tx];
    __syncthreads();
#pragma unroll
    for (int j = 0; j < 4; j++) {
        const uint32_t n = bn + ty + j * 8, k = bk + tx;
        const size_t tbase = ((size_t)(n >> 7) * NCH + (k >> 6)) << 14;
        *(__nv_bfloat16*)(Wt + tbase + SWZ((n & 127) * 128 + (k & 63) * 2)) =
            __float2bfloat16(t[tx][ty + j * 8]);
    }
}

__global__ void finalize(const float* __restrict__ n0, const float* __restrict__ n1,
                         const float* __restrict__ d0, const float* __restrict__ d1,
                         float* __restrict__ out)
{
    const int i = blockIdx.x * blockDim.x + threadIdx.x;
    out[i] = (n0[i] + n1[i]) / (d0[i] + d1[i] + 1e-7f);
}

// ---------------------------------------------------------------------------
// Phase 1 (merged Q & K via blockIdx.z): blocked-tile GEMM, bulk-copy loads.
// Ring-3 slots with full/empty mbarrier pairs (R13, proven).
// ---------------------------------------------------------------------------
#define P1_SMEM (1024 + 6*TILE_BYTES + 512)

__global__ void __launch_bounds__(256, 2)
gemm_bias_mma(const __nv_bfloat16* __restrict__ A1, const __nv_bfloat16* __restrict__ A2,
              const __nv_bfloat16* __restrict__ B1, const __nv_bfloat16* __restrict__ B2,
              const float* __restrict__ bias1, const float* __restrict__ bias2,
              __nv_bfloat16* __restrict__ O1, __nv_bfloat16* __restrict__ O2)
{
    extern __shared__ __align__(16) char smem[];
    const uint32_t sb = smem_u32(smem);
    const int tid = threadIdx.x, lane = tid & 31, wid = tid >> 5;
    const int wm = wid >> 1, wn = wid & 1;
    const int n0 = blockIdx.x * 128, m0 = blockIdx.y * 128;
    const int z = blockIdx.z;

    const char* A  = (const char*)(z ? A2 : A1);
    const char* Bt = (const char*)(z ? B2 : B1);
    const float* bias = z ? bias2 : bias1;
    char* Out = (char*)(z ? O2 : O1);

    const uint32_t MBF = sb + 8, MBE = sb + 32;
    float* bias_s = (float*)(smem + 1024 + 6*TILE_BYTES);
    if (tid == 0) {
        MBARRIER_INIT(MBF + 0, 1);   MBARRIER_INIT(MBF + 8, 1);   MBARRIER_INIT(MBF + 16, 1);
        MBARRIER_INIT(MBE + 0, 256); MBARRIER_INIT(MBE + 8, 256); MBARRIER_INIT(MBE + 16, 256);
    }
    if (tid < 128) bias_s[tid] = bias[n0 + tid];
    __syncthreads();

    const uint32_t seg = (uint32_t)(lane >> 4) * 16;
    const uint32_t aoffp0 = (uint32_t)(wm * 32 + (lane & 15)) * 128 + seg;
    const uint32_t aswz0 = SWZ(aoffp0);
    const uint32_t aswz1 = SWZ(aoffp0 + 16 * 128);
    const uint32_t bswz0 = SWZ((uint32_t)(wn * 64 + (lane & 15)) * 128 + seg);

#define ASLOT(s) (sb + 1024 + (s) * TILE_BYTES)
#define BSLOT(s) (sb + 1024 + 3*TILE_BYTES + (s) * TILE_BYTES)
#define GISSUE(cc, S) do { \
        MBARRIER_EXPECT_TX(MBF + 8 * (S), 2 * TILE_BYTES); \
        bulk_g2s(ASLOT(S), A  + (((size_t)(m0 >> 7) * NCH + (cc)) << 14), \
                 TILE_BYTES, MBF + 8 * (S)); \
        bulk_g2s(BSLOT(S), Bt + (((size_t)(n0 >> 7) * NCH + (cc)) << 14), \
                 TILE_BYTES, MBF + 8 * (S)); \
    } while (0)

    float acc[2][8][4];
#pragma unroll
    for (int i = 0; i < 2; i++)
#pragma unroll
        for (int j = 0; j < 8; j++)
#pragma unroll
            for (int q = 0; q < 4; q++) acc[i][j][q] = 0.f;

    if (tid == 0) { GISSUE(0, 0); GISSUE(1, 1); GISSUE(2, 2); }

    int phf0 = 0, phf1 = 0, phf2 = 0;
    int phe0 = 0, phe1 = 0, phe2 = 0;

#define GBODY(cc, S, PHF, PHE) do { \
        MBARRIER_WAIT_PARITY(MBF + 8 * (S), PHF); PHF ^= 1; \
        CHUNK_MMA_SW(ASLOT(S), BSLOT(S)); \
        MBARRIER_ARRIVE(MBE + 8 * (S)); \
        if ((cc) + 3 < NCH && tid == 0) { \
            MBARRIER_WAIT_PARITY(MBE + 8 * (S), PHE); PHE ^= 1; \
            GISSUE((cc) + 3, S); \
        } \
    } while (0)

#pragma unroll
    for (int c0 = 0; c0 < NCH; c0 += 3) {
        GBODY(c0,     0, phf0, phe0);
        GBODY(c0 + 1, 1, phf1, phe1);
        GBODY(c0 + 2, 2, phf2, phe2);
    }
#undef GBODY
#undef GISSUE
#undef ASLOT
#undef BSLOT

#pragma unroll
    for (int mt = 0; mt < 2; mt++) {
        const uint32_t row0 = (uint32_t)(wm * 32 + mt * 16 + (lane >> 2));
#pragma unroll
        for (int nt = 0; nt < 8; nt++) {
            const int nl = wn * 64 + nt * 8 + (lane & 3) * 2;
            const float b0 = bias_s[nl], b1 = bias_s[nl + 1];
            __nv_bfloat162 p0 = __floats2bfloat162_rn(acc[mt][nt][0] + b0, acc[mt][nt][1] + b1);
            __nv_bfloat162 p1 = __floats2bfloat162_rn(acc[mt][nt][2] + b0, acc[mt][nt][3] + b1);
            const size_t tb = ((size_t)(m0 >> 7) * NCH + (n0 >> 6) + wn) << 14;
            const uint32_t col2 = (uint32_t)(nt * 8 + (lane & 3) * 2) * 2;
            *(uint32_t*)(Out + tb + SWZ(row0 * 128 + col2))       = *(uint32_t*)&p0;
            *(uint32_t*)(Out + tb + SWZ((row0 + 8) * 128 + col2)) = *(uint32_t*)&p1;
        }
    }
}

// ---------------------------------------------------------------------------
// Phase 2: 512 threads, 16 warps (4m x 4n), 32x32 warp tiles — doubles
// warps/SM at equal smem traffic. Ring-3 full/empty mbarrier pipeline.
// SMEM: [8) full x3 | [32) empty x3 | [64) num | [576) den | [2048) rings
// ---------------------------------------------------------------------------
#define P2_SMEM (2048 + 6*TILE_BYTES)
#define GTOT (8*NCH)   // 96

__global__ void __launch_bounds__(512, 2)
attn_mma(const __nv_bfloat16* __restrict__ Q, const __nv_bfloat16* __restrict__ K,
         float* __restrict__ gnum0, float* __restrict__ gnum1,
         float* __restrict__ gden0, float* __restrict__ gden1)
{
    extern __shared__ __align__(16) char smem[];
    const uint32_t sb = smem_u32(smem);
    float* num_sh = (float*)(smem + 64);
    float* den_sh = (float*)(smem + 576);
    const int tid = threadIdx.x, lane = tid & 31, wid = tid >> 5;
    const int wm = wid >> 2, wn = wid & 3;    // 4m x 4n
    const int t0 = blockIdx.x * 128, b = blockIdx.y, sh = blockIdx.z;
    const uint32_t MBF = sb + 8, MBE = sb + 32;

    const char* Qb = (const char*)Q;
    const char* Kb = (const char*)K;
    const int ktile = b * 16 + blockIdx.x;
    const int qtile0 = b * 16 + sh * 8;

    if (tid == 0) {
        MBARRIER_INIT(MBF + 0, 1);   MBARRIER_INIT(MBF + 8, 1);   MBARRIER_INIT(MBF + 16, 1);
        MBARRIER_INIT(MBE + 0, 512); MBARRIER_INIT(MBE + 8, 512); MBARRIER_INIT(MBE + 16, 512);
    }
    if (tid < 128) { num_sh[tid] = 0.f; den_sh[tid] = 0.f; }
    __syncthreads();

    const uint32_t seg = (uint32_t)(lane >> 4) * 16;
    const uint32_t aoffp0 = (uint32_t)(wm * 32 + (lane & 15)) * 128 + seg;
    const uint32_t aswz0 = SWZ(aoffp0);
    const uint32_t aswz1 = SWZ(aoffp0 + 16 * 128);
    const uint32_t bswz0 = SWZ((uint32_t)(wn * 32 + (lane & 15)) * 128 + seg);

#define QSLOT(s) (sb + 2048 + (s) * TILE_BYTES)
#define KSLOT(s) (sb + 2048 + 3*TILE_BYTES + (s) * TILE_BYTES)
#define AISSUE(gg, S) do { \
        const int _st = (gg) / NCH, _cc = (gg) % NCH; \
        MBARRIER_EXPECT_TX(MBF + 8 * (S), 2 * TILE_BYTES); \
        bulk_g2s(QSLOT(S), Qb + (((size_t)(qtile0 + _st) * NCH + _cc) << 14), \
                 TILE_BYTES, MBF + 8 * (S)); \
        bulk_g2s(KSLOT(S), Kb + (((size_t)ktile * NCH + _cc) << 14), \
                 TILE_BYTES, MBF + 8 * (S)); \
    } while (0)

    // per-tile epilogue: e = exp(tanh(qk)); reduce over s into num/den per t
#define EPI() do { \
        _Pragma("unroll") \
        for (int nt = 0; nt < 4; nt++) { \
            float vn0 = 0.f, vn1 = 0.f, vd0 = 0.f, vd1 = 0.f; \
            _Pragma("unroll") \
            for (int mt = 0; mt < 2; mt++) { \
                const float q0 = acc[mt][nt][0], q1 = acc[mt][nt][1]; \
                const float q2 = acc[mt][nt][2], q3 = acc[mt][nt][3]; \
                const float e0 = __expf(fast_tanh(q0)); \
                const float e1 = __expf(fast_tanh(q1)); \
                const float e2 = __expf(fast_tanh(q2)); \
                const float e3 = __expf(fast_tanh(q3)); \
                vn0 += e0 * q0 + e2 * q2;  vd0 += e0 + e2; \
                vn1 += e1 * q1 + e3 * q3;  vd1 += e1 + e3; \
            } \
            _Pragma("unroll") \
            for (int o = 4; o <= 16; o <<= 1) { \
                vn0 += __shfl_xor_sync(0xFFFFFFFFu, vn0, o); \
                vn1 += __shfl_xor_sync(0xFFFFFFFFu, vn1, o); \
                vd0 += __shfl_xor_sync(0xFFFFFFFFu, vd0, o); \
                vd1 += __shfl_xor_sync(0xFFFFFFFFu, vd1, o); \
            } \
            if (lane < 4) { \
                const int col = wn * 32 + nt * 8 + lane * 2; \
                atomicAdd(&num_sh[col],     vn0); \
                atomicAdd(&num_sh[col + 1], vn1); \
                atomicAdd(&den_sh[col],     vd0); \
                atomicAdd(&den_sh[col + 1], vd1); \
            } \
        } \
        _Pragma("unroll") \
        for (int i = 0; i < 2; i++) \
            _Pragma("unroll") \
            for (int j = 0; j < 4; j++) \
                _Pragma("unroll") \
                for (int q = 0; q < 4; q++) acc[i][j][q] = 0.f; \
    } while (0)

    float acc[2][4][4];
#pragma unroll
    for (int i = 0; i < 2; i++)
#pragma unroll
        for (int j = 0; j < 4; j++)
#pragma unroll
            for (int q = 0; q < 4; q++) acc[i][j][q] = 0.f;

    if (tid == 0) { AISSUE(0, 0); AISSUE(1, 1); AISSUE(2, 2); }

    int phf0 = 0, phf1 = 0, phf2 = 0;
    int phe0 = 0, phe1 = 0, phe2 = 0;

#define ABODY(gg, S, PHF, PHE, DO_EPI) do { \
        MBARRIER_WAIT_PARITY(MBF + 8 * (S), PHF); PHF ^= 1; \
        CHUNK_MMA_SW16(QSLOT(S), KSLOT(S)); \
        MBARRIER_ARRIVE(MBE + 8 * (S)); \
        if (DO_EPI) EPI(); \
        if ((gg) + 3 < GTOT && tid == 0) { \
            MBARRIER_WAIT_PARITY(MBE + 8 * (S), PHE); PHE ^= 1; \
            AISSUE((gg) + 3, S); \
        } \
    } while (0)

    for (int g0 = 0; g0 < GTOT; g0 += 3) {
        ABODY(g0,     0, phf0, phe0, false);
        ABODY(g0 + 1, 1, phf1, phe1, false);
        // tiles are 12 chunks; last chunk of a tile lands at g0%12==9, slot 2
        ABODY(g0 + 2, 2, phf2, phe2, (g0 % NCH) == 9);
    }
#undef ABODY
#undef AISSUE
#undef QSLOT
#undef KSLOT
#undef EPI

    __syncthreads();
    if (tid < 128) {
        float* gn = sh ? gnum1 : gnum0;
        float* gd = sh ? gden1 : gden0;
        gn[(size_t)b * SEQ + t0 + tid] = num_sh[tid];
        gd[(size_t)b * SEQ + t0 + tid] = den_sh[tid];
    }
}

// ---------------------------------------------------------------------------
extern "C" void kernel_launch(void* const* d_in, const int* in_sizes, int n_in,
                              void* d_out, int out_size)
{
    const float* x1 = (const float*)d_in[0];
    const float* x2 = (const float*)d_in[1];
    const float* Wq = (const float*)d_in[2];
    const float* bq = (const float*)d_in[3];
    const float* Wk = (const float*)d_in[4];
    const float* bk = (const float*)d_in[5];
    float* out = (float*)d_out;

    __nv_bfloat16 *X1b, *X2b, *Qp, *Kp, *Wqt, *Wkt;
    float *gnum, *gden;
    cudaGetSymbolAddress((void**)&X1b, g_X1b);
    cudaGetSymbolAddress((void**)&X2b, g_X2b);
    cudaGetSymbolAddress((void**)&Qp,  g_Q);
    cudaGetSymbolAddress((void**)&Kp,  g_K);
    cudaGetSymbolAddress((void**)&Wqt, g_Wqt);
    cudaGetSymbolAddress((void**)&Wkt, g_Wkt);
    cudaGetSymbolAddress((void**)&gnum, g_num);
    cudaGetSymbolAddress((void**)&gden, g_den);
    float* gnum1 = gnum + BATCH*SEQ;
    float* gden1 = gden + BATCH*SEQ;

    cudaFuncSetAttribute(gemm_bias_mma, cudaFuncAttributeMaxDynamicSharedMemorySize, P1_SMEM);
    cudaFuncSetAttribute(attn_mma,      cudaFuncAttributeMaxDynamicSharedMemorySize, P2_SMEM);

    const int nconv = (int)(((size_t)MTOT * DIM / 8) / 256);   // 6144 blocks
    convert_bf16_2<<<dim3(nconv, 1, 2), 256>>>(x1, x2, X1b, X2b);

    dim3 tgrid(DIM / 32, DIM / 32, 2);
    transpose_bf16_2<<<tgrid, dim3(32, 8)>>>(Wq, Wk, Wqt, Wkt);

    dim3 ggrid(DIM / 128, MTOT / 128, 2);   // (6, 128, 2) = 1536 CTAs
    gemm_bias_mma<<<ggrid, 256, P1_SMEM>>>(X1b, X2b, Wqt, Wkt, bq, bk, Qp, Kp);

    dim3 agrid(SEQ / 128, BATCH, 2);        // (16, 8, 2) = 256 CTAs
    attn_mma<<<agrid, 512, P2_SMEM>>>(Qp, Kp, gnum, gnum1, gden, gden1);

    finalize<<<BATCH*SEQ/256, 256>>>(gnum, gnum1, gden, gden1, out);
}

// round 15
// speedup vs baseline: 1.0506x; 1.0506x over previous
#include <cuda_runtime.h>
#include <cuda_bf16.h>
#include <cstdint>
#include <cstddef>

#define BATCH 8
#define SEQ   2048
#define DIM   768
#define MTOT  (BATCH*SEQ)   // 16384
#define NCH   12            // 768 / 64 k-chunks
#define TILE_BYTES 16384    // one (128-row x 64-k) bf16 tile, SW128-swizzled

// ---------------- scratch (no dynamic allocation allowed) -------------------
__device__ __align__(256) __nv_bfloat16 g_X1b[(size_t)MTOT*DIM];
__device__ __align__(256) __nv_bfloat16 g_X2b[(size_t)MTOT*DIM];
__device__ __align__(256) __nv_bfloat16 g_Q  [(size_t)MTOT*DIM];
__device__ __align__(256) __nv_bfloat16 g_K  [(size_t)MTOT*DIM];
__device__ __align__(256) __nv_bfloat16 g_Wqt[(size_t)DIM*DIM];
__device__ __align__(256) __nv_bfloat16 g_Wkt[(size_t)DIM*DIM];
__device__ float g_num[2][BATCH*SEQ];
__device__ float g_den[2][BATCH*SEQ];

// ---------------- helpers ----------------------------------------------------
#define SWZ(o) ((o) ^ (((o) >> 3) & 0x70))

__device__ __forceinline__ uint32_t smem_u32(const void* p) {
    uint32_t a;
    asm("{ .reg .u64 t; cvta.to.shared.u64 t, %1; cvt.u32.u64 %0, t; }"
        : "=r"(a) : "l"(p));
    return a;
}
__device__ __forceinline__ void ldsm_x4(uint32_t* r, uint32_t addr) {
    asm volatile("ldmatrix.sync.aligned.m8n8.x4.shared.b16 {%0,%1,%2,%3}, [%4];"
                 : "=r"(r[0]), "=r"(r[1]), "=r"(r[2]), "=r"(r[3]) : "r"(addr));
}
__device__ __forceinline__ void mma_bf16(float* c, const uint32_t* a,
                                         uint32_t b0, uint32_t b1) {
    asm volatile(
        "mma.sync.aligned.m16n8k16.row.col.f32.bf16.bf16.f32 "
        "{%0,%1,%2,%3}, {%4,%5,%6,%7}, {%8,%9}, {%0,%1,%2,%3};"
        : "+f"(c[0]), "+f"(c[1]), "+f"(c[2]), "+f"(c[3])
        : "r"(a[0]), "r"(a[1]), "r"(a[2]), "r"(a[3]), "r"(b0), "r"(b1));
}
__device__ __forceinline__ float fast_tanh(float x) {
    float y; asm("tanh.approx.f32 %0, %1;" : "=f"(y) : "f"(x)); return y;
}

// mbarrier + bulk-copy primitives (Hopper+ PTX; valid on plain sm_103)
#define MBARRIER_INIT(addr, cnt) \
    asm volatile("mbarrier.init.shared.b64 [%0], %1;" :: "r"(addr), "r"(cnt) : "memory")
#define MBARRIER_EXPECT_TX(addr, bytes) \
    asm volatile("mbarrier.arrive.expect_tx.shared.b64 _, [%0], %1;" \
                 :: "r"(addr), "r"(bytes) : "memory")
#define MBARRIER_ARRIVE(addr) \
    asm volatile("mbarrier.arrive.release.cta.shared.b64 _, [%0];" \
                 :: "r"(addr) : "memory")
#define MBARRIER_WAIT_PARITY(mbar, par) do { \
    uint32_t _m = (uint32_t)(mbar), _p = (uint32_t)(par), _d; \
    asm volatile("{\n\t.reg .pred p;\n\t" \
        "mbarrier.try_wait.parity.acquire.cta.shared::cta.b64 p, [%1], %2;\n\t" \
        "selp.b32 %0, 1, 0, p;\n\t}" : "=r"(_d) : "r"(_m), "r"(_p) : "memory"); \
    if (!_d) { \
        asm volatile("{\n\t.reg .pred P1;\n\t" \
            "WL_%=:\n\t" \
            "mbarrier.try_wait.parity.acquire.cta.shared::cta.b64 P1, [%0], %1, 0x989680;\n\t" \
            "@P1 bra.uni WD_%=;\n\t" \
            "bra.uni WL_%=;\n\t" \
            "WD_%=:\n\t}" :: "r"(_m), "r"(_p) : "memory"); \
    } \
} while (0)
__device__ __forceinline__ void bulk_g2s(uint32_t dst, const void* src,
                                         uint32_t bytes, uint32_t mbar) {
    asm volatile(
        "cp.async.bulk.shared::cluster.global.mbarrier::complete_tx::bytes "
        "[%0], [%1], %2, [%3];"
        :: "r"(dst), "l"(src), "r"(bytes), "r"(mbar) : "memory");
}

// 128x128x64 chunk MMA (8 warps, 32x64 warp tiles), XOR-folded addressing.
#define CHUNK_MMA_SW(AsX, BsX) do { \
    const uint32_t _Ab0 = (AsX) + aswz0; \
    const uint32_t _Ab1 = (AsX) + aswz1; \
    const uint32_t _Bb  = (BsX) + bswz0; \
    _Pragma("unroll") \
    for (int ks = 0; ks < 4; ks++) { \
        const uint32_t _kx = ks * 32; \
        uint32_t a0[4], a1[4], bmA[4], bmB[4]; \
        ldsm_x4(a0,  _Ab0 ^ _kx); \
        ldsm_x4(a1,  _Ab1 ^ _kx); \
        ldsm_x4(bmA, _Bb ^ _kx); \
        _Pragma("unroll") \
        for (int np = 0; np < 4; np++) { \
            uint32_t* bc = (np & 1) ? bmB : bmA; \
            uint32_t* bn_ = (np & 1) ? bmA : bmB; \
            if (np < 3) \
                ldsm_x4(bn_, (_Bb + (np + 1) * 2048) ^ _kx); \
            mma_bf16(acc[0][np*2],   a0, bc[0], bc[2]); \
            mma_bf16(acc[0][np*2+1], a0, bc[1], bc[3]); \
            mma_bf16(acc[1][np*2],   a1, bc[0], bc[2]); \
            mma_bf16(acc[1][np*2+1], a1, bc[1], bc[3]); \
        } \
    } \
} while (0)

// ---------------------------------------------------------------------------
// convert: f32 row-major -> bf16 blocked SW128 tiles
// ---------------------------------------------------------------------------
__global__ void convert_bf16_2(const float* __restrict__ x1, const float* __restrict__ x2,
                               __nv_bfloat16* __restrict__ y1, __nv_bfloat16* __restrict__ y2)
{
    const float* x = blockIdx.z ? x2 : x1;
    char* y = (char*)(blockIdx.z ? y2 : y1);
    const size_t i = ((size_t)blockIdx.x * blockDim.x + threadIdx.x) * 8;
    const uint32_t m = (uint32_t)(i / DIM), k = (uint32_t)(i % DIM);
    float4 v0 = *(const float4*)(x + i);
    float4 v1 = *(const float4*)(x + i + 4);
    __nv_bfloat162 a = __floats2bfloat162_rn(v0.x, v0.y);
    __nv_bfloat162 b = __floats2bfloat162_rn(v0.z, v0.w);
    __nv_bfloat162 c = __floats2bfloat162_rn(v1.x, v1.y);
    __nv_bfloat162 d = __floats2bfloat162_rn(v1.z, v1.w);
    uint4 st; st.x = *(uint32_t*)&a; st.y = *(uint32_t*)&b;
    st.z = *(uint32_t*)&c; st.w = *(uint32_t*)&d;
    const size_t tbase = ((size_t)(m >> 7) * NCH + (k >> 6)) << 14;
    *(uint4*)(y + tbase + SWZ((m & 127) * 128 + (k & 63) * 2)) = st;
}

// transpose: W[k][n] f32 -> Wt blocked SW128 tiles over (n-tile, k-chunk)
__global__ void transpose_bf16_2(const float* __restrict__ W1, const float* __restrict__ W2,
                                 __nv_bfloat16* __restrict__ T1, __nv_bfloat16* __restrict__ T2)
{
    const float* W = blockIdx.z ? W2 : W1;
    char* Wt = (char*)(blockIdx.z ? T2 : T1);
    __shared__ float t[32][33];
    int tx = threadIdx.x, ty = threadIdx.y;
    int bk = blockIdx.y * 32, bn = blockIdx.x * 32;
#pragma unroll
    for (int j = 0; j < 4; j++)
        t[ty + j * 8][tx] = W[(size_t)(bk + ty + j * 8) * DIM + bn + tx];
    __syncthreads();
#pragma unroll
    for (int j = 0; j < 4; j++) {
        const uint32_t n = bn + ty + j * 8, k = bk + tx;
        const size_t tbase = ((size_t)(n >> 7) * NCH + (k >> 6)) << 14;
        *(__nv_bfloat16*)(Wt + tbase + SWZ((n & 127) * 128 + (k & 63) * 2)) =
            __float2bfloat16(t[tx][ty + j * 8]);
    }
}

__global__ void finalize(const float* __restrict__ n0, const float* __restrict__ n1,
                         const float* __restrict__ d0, const float* __restrict__ d1,
                         float* __restrict__ out)
{
    const int i = blockIdx.x * blockDim.x + threadIdx.x;
    out[i] = (n0[i] + n1[i]) / (d0[i] + d1[i] + 1e-7f);
}

// ---------------------------------------------------------------------------
// Phase 1 (merged Q & K via blockIdx.z): blocked-tile GEMM, bulk-copy loads.
// Ring-3 slots with full/empty mbarrier pairs (R13, proven). Unchanged.
// ---------------------------------------------------------------------------
#define P1_SMEM (1024 + 6*TILE_BYTES + 512)

__global__ void __launch_bounds__(256, 2)
gemm_bias_mma(const __nv_bfloat16* __restrict__ A1, const __nv_bfloat16* __restrict__ A2,
              const __nv_bfloat16* __restrict__ B1, const __nv_bfloat16* __restrict__ B2,
              const float* __restrict__ bias1, const float* __restrict__ bias2,
              __nv_bfloat16* __restrict__ O1, __nv_bfloat16* __restrict__ O2)
{
    extern __shared__ __align__(16) char smem[];
    const uint32_t sb = smem_u32(smem);
    const int tid = threadIdx.x, lane = tid & 31, wid = tid >> 5;
    const int wm = wid >> 1, wn = wid & 1;
    const int n0 = blockIdx.x * 128, m0 = blockIdx.y * 128;
    const int z = blockIdx.z;

    const char* A  = (const char*)(z ? A2 : A1);
    const char* Bt = (const char*)(z ? B2 : B1);
    const float* bias = z ? bias2 : bias1;
    char* Out = (char*)(z ? O2 : O1);

    const uint32_t MBF = sb + 8, MBE = sb + 32;
    float* bias_s = (float*)(smem + 1024 + 6*TILE_BYTES);
    if (tid == 0) {
        MBARRIER_INIT(MBF + 0, 1);   MBARRIER_INIT(MBF + 8, 1);   MBARRIER_INIT(MBF + 16, 1);
        MBARRIER_INIT(MBE + 0, 256); MBARRIER_INIT(MBE + 8, 256); MBARRIER_INIT(MBE + 16, 256);
    }
    if (tid < 128) bias_s[tid] = bias[n0 + tid];
    __syncthreads();

    const uint32_t seg = (uint32_t)(lane >> 4) * 16;
    const uint32_t aoffp0 = (uint32_t)(wm * 32 + (lane & 15)) * 128 + seg;
    const uint32_t aswz0 = SWZ(aoffp0);
    const uint32_t aswz1 = SWZ(aoffp0 + 16 * 128);
    const uint32_t bswz0 = SWZ((uint32_t)(wn * 64 + (lane & 15)) * 128 + seg);

#define ASLOT(s) (sb + 1024 + (s) * TILE_BYTES)
#define BSLOT(s) (sb + 1024 + 3*TILE_BYTES + (s) * TILE_BYTES)
#define GISSUE(cc, S) do { \
        MBARRIER_EXPECT_TX(MBF + 8 * (S), 2 * TILE_BYTES); \
        bulk_g2s(ASLOT(S), A  + (((size_t)(m0 >> 7) * NCH + (cc)) << 14), \
                 TILE_BYTES, MBF + 8 * (S)); \
        bulk_g2s(BSLOT(S), Bt + (((size_t)(n0 >> 7) * NCH + (cc)) << 14), \
                 TILE_BYTES, MBF + 8 * (S)); \
    } while (0)

    float acc[2][8][4];
#pragma unroll
    for (int i = 0; i < 2; i++)
#pragma unroll
        for (int j = 0; j < 8; j++)
#pragma unroll
            for (int q = 0; q < 4; q++) acc[i][j][q] = 0.f;

    if (tid == 0) { GISSUE(0, 0); GISSUE(1, 1); GISSUE(2, 2); }

    int phf0 = 0, phf1 = 0, phf2 = 0;
    int phe0 = 0, phe1 = 0, phe2 = 0;

#define GBODY(cc, S, PHF, PHE) do { \
        MBARRIER_WAIT_PARITY(MBF + 8 * (S), PHF); PHF ^= 1; \
        CHUNK_MMA_SW(ASLOT(S), BSLOT(S)); \
        MBARRIER_ARRIVE(MBE + 8 * (S)); \
        if ((cc) + 3 < NCH && tid == 0) { \
            MBARRIER_WAIT_PARITY(MBE + 8 * (S), PHE); PHE ^= 1; \
            GISSUE((cc) + 3, S); \
        } \
    } while (0)

#pragma unroll
    for (int c0 = 0; c0 < NCH; c0 += 3) {
        GBODY(c0,     0, phf0, phe0);
        GBODY(c0 + 1, 1, phf1, phe1);
        GBODY(c0 + 2, 2, phf2, phe2);
    }
#undef GBODY
#undef GISSUE
#undef ASLOT
#undef BSLOT

#pragma unroll
    for (int mt = 0; mt < 2; mt++) {
        const uint32_t row0 = (uint32_t)(wm * 32 + mt * 16 + (lane >> 2));
#pragma unroll
        for (int nt = 0; nt < 8; nt++) {
            const int nl = wn * 64 + nt * 8 + (lane & 3) * 2;
            const float b0 = bias_s[nl], b1 = bias_s[nl + 1];
            __nv_bfloat162 p0 = __floats2bfloat162_rn(acc[mt][nt][0] + b0, acc[mt][nt][1] + b1);
            __nv_bfloat162 p1 = __floats2bfloat162_rn(acc[mt][nt][2] + b0, acc[mt][nt][3] + b1);
            const size_t tb = ((size_t)(m0 >> 7) * NCH + (n0 >> 6) + wn) << 14;
            const uint32_t col2 = (uint32_t)(nt * 8 + (lane & 3) * 2) * 2;
            *(uint32_t*)(Out + tb + SWZ(row0 * 128 + col2))       = *(uint32_t*)&p0;
            *(uint32_t*)(Out + tb + SWZ((row0 + 8) * 128 + col2)) = *(uint32_t*)&p1;
        }
    }
}

// ---------------------------------------------------------------------------
// Phase 2: R13 8-warp consumer layout + DEDICATED PRODUCER WARP (warp 8).
// 288 threads: tid<256 = 8 MMA warps (32x64 tiles), tid>=256 = producer.
// Consumers: wait full -> CHUNK_MMA -> arrive empty (never wait empty).
// Producer (1 thread): waits empty[s], issues bulk copies immediately.
// SMEM: [8) full x3 | [32) empty x3 | [64) num | [576) den | [2048) rings
// ---------------------------------------------------------------------------
#define P2_SMEM (2048 + 6*TILE_BYTES)
#define GTOT (8*NCH)   // 96

__global__ void __launch_bounds__(288, 2)
attn_mma(const __nv_bfloat16* __restrict__ Q, const __nv_bfloat16* __restrict__ K,
         float* __restrict__ gnum0, float* __restrict__ gnum1,
         float* __restrict__ gden0, float* __restrict__ gden1)
{
    extern __shared__ __align__(16) char smem[];
    const uint32_t sb = smem_u32(smem);
    float* num_sh = (float*)(smem + 64);
    float* den_sh = (float*)(smem + 576);
    const int tid = threadIdx.x, lane = tid & 31, wid = tid >> 5;
    const int wm = wid >> 1, wn = wid & 1;
    const int t0 = blockIdx.x * 128, b = blockIdx.y, sh = blockIdx.z;
    const uint32_t MBF = sb + 8, MBE = sb + 32;

    const char* Qb = (const char*)Q;
    const char* Kb = (const char*)K;
    const int ktile = b * 16 + blockIdx.x;
    const int qtile0 = b * 16 + sh * 8;

    if (tid == 0) {
        MBARRIER_INIT(MBF + 0, 1);   MBARRIER_INIT(MBF + 8, 1);   MBARRIER_INIT(MBF + 16, 1);
        MBARRIER_INIT(MBE + 0, 256); MBARRIER_INIT(MBE + 8, 256); MBARRIER_INIT(MBE + 16, 256);
    }
    if (tid < 128) { num_sh[tid] = 0.f; den_sh[tid] = 0.f; }
    __syncthreads();

#define QSLOT(s) (sb + 2048 + (s) * TILE_BYTES)
#define KSLOT(s) (sb + 2048 + 3*TILE_BYTES + (s) * TILE_BYTES)
#define AISSUE(gg, S) do { \
        const int _st = (gg) / NCH, _cc = (gg) % NCH; \
        MBARRIER_EXPECT_TX(MBF + 8 * (S), 2 * TILE_BYTES); \
        bulk_g2s(QSLOT(S), Qb + (((size_t)(qtile0 + _st) * NCH + _cc) << 14), \
                 TILE_BYTES, MBF + 8 * (S)); \
        bulk_g2s(KSLOT(S), Kb + (((size_t)ktile * NCH + _cc) << 14), \
                 TILE_BYTES, MBF + 8 * (S)); \
    } while (0)

    if (tid >= 256) {
        // ---------------- producer warp (thread 256 active) ----------------
        if (tid == 256) {
            AISSUE(0, 0); AISSUE(1, 1); AISSUE(2, 2);
            int phe0 = 0, phe1 = 0, phe2 = 0;
#pragma unroll 1
            for (int g0 = 0; g0 + 3 < GTOT; g0 += 3) {
                MBARRIER_WAIT_PARITY(MBE + 0, phe0);  phe0 ^= 1;  AISSUE(g0 + 3, 0);
                if (g0 + 4 < GTOT) { MBARRIER_WAIT_PARITY(MBE + 8, phe1);  phe1 ^= 1;  AISSUE(g0 + 4, 1); }
                if (g0 + 5 < GTOT) { MBARRIER_WAIT_PARITY(MBE + 16, phe2); phe2 ^= 1;  AISSUE(g0 + 5, 2); }
            }
        }
    } else {
        // ---------------- consumer warps (8 x 32x64 tiles) ----------------
        const uint32_t seg = (uint32_t)(lane >> 4) * 16;
        const uint32_t aoffp0 = (uint32_t)(wm * 32 + (lane & 15)) * 128 + seg;
        const uint32_t aswz0 = SWZ(aoffp0);
        const uint32_t aswz1 = SWZ(aoffp0 + 16 * 128);
        const uint32_t bswz0 = SWZ((uint32_t)(wn * 64 + (lane & 15)) * 128 + seg);

#define EPI() do { \
        _Pragma("unroll") \
        for (int nt = 0; nt < 8; nt++) { \
            float vn0 = 0.f, vn1 = 0.f, vd0 = 0.f, vd1 = 0.f; \
            _Pragma("unroll") \
            for (int mt = 0; mt < 2; mt++) { \
                const float q0 = acc[mt][nt][0], q1 = acc[mt][nt][1]; \
                const float q2 = acc[mt][nt][2], q3 = acc[mt][nt][3]; \
                const float e0 = __expf(fast_tanh(q0)); \
                const float e1 = __expf(fast_tanh(q1)); \
                const float e2 = __expf(fast_tanh(q2)); \
                const float e3 = __expf(fast_tanh(q3)); \
                vn0 += e0 * q0 + e2 * q2;  vd0 += e0 + e2; \
                vn1 += e1 * q1 + e3 * q3;  vd1 += e1 + e3; \
            } \
            _Pragma("unroll") \
            for (int o = 4; o <= 16; o <<= 1) { \
                vn0 += __shfl_xor_sync(0xFFFFFFFFu, vn0, o); \
                vn1 += __shfl_xor_sync(0xFFFFFFFFu, vn1, o); \
                vd0 += __shfl_xor_sync(0xFFFFFFFFu, vd0, o); \
                vd1 += __shfl_xor_sync(0xFFFFFFFFu, vd1, o); \
            } \
            if (lane < 4) { \
                const int col = wn * 64 + nt * 8 + lane * 2; \
                atomicAdd(&num_sh[col],     vn0); \
                atomicAdd(&num_sh[col + 1], vn1); \
                atomicAdd(&den_sh[col],     vd0); \
                atomicAdd(&den_sh[col + 1], vd1); \
            } \
        } \
        _Pragma("unroll") \
        for (int i = 0; i < 2; i++) \
            _Pragma("unroll") \
            for (int j = 0; j < 8; j++) \
                _Pragma("unroll") \
                for (int q = 0; q < 4; q++) acc[i][j][q] = 0.f; \
    } while (0)

        float acc[2][8][4];
#pragma unroll
        for (int i = 0; i < 2; i++)
#pragma unroll
            for (int j = 0; j < 8; j++)
#pragma unroll
                for (int q = 0; q < 4; q++) acc[i][j][q] = 0.f;

        int phf0 = 0, phf1 = 0, phf2 = 0;

#define CBODY(gg, S, PHF, DO_EPI) do { \
        MBARRIER_WAIT_PARITY(MBF + 8 * (S), PHF); PHF ^= 1; \
        CHUNK_MMA_SW(QSLOT(S), KSLOT(S)); \
        MBARRIER_ARRIVE(MBE + 8 * (S)); \
        if (DO_EPI) EPI(); \
    } while (0)

        for (int g0 = 0; g0 < GTOT; g0 += 3) {
            CBODY(g0,     0, phf0, false);
            CBODY(g0 + 1, 1, phf1, false);
            // tiles are 12 chunks; tile-final chunk lands at slot 2 when g0%12==9
            CBODY(g0 + 2, 2, phf2, (g0 % NCH) == 9);
        }
#undef CBODY
#undef EPI
    }
#undef AISSUE
#undef QSLOT
#undef KSLOT

    __syncthreads();
    if (tid < 128) {
        float* gn = sh ? gnum1 : gnum0;
        float* gd = sh ? gden1 : gden0;
        gn[(size_t)b * SEQ + t0 + tid] = num_sh[tid];
        gd[(size_t)b * SEQ + t0 + tid] = den_sh[tid];
    }
}

// ---------------------------------------------------------------------------
extern "C" void kernel_launch(void* const* d_in, const int* in_sizes, int n_in,
                              void* d_out, int out_size)
{
    const float* x1 = (const float*)d_in[0];
    const float* x2 = (const float*)d_in[1];
    const float* Wq = (const float*)d_in[2];
    const float* bq = (const float*)d_in[3];
    const float* Wk = (const float*)d_in[4];
    const float* bk = (const float*)d_in[5];
    float* out = (float*)d_out;

    __nv_bfloat16 *X1b, *X2b, *Qp, *Kp, *Wqt, *Wkt;
    float *gnum, *gden;
    cudaGetSymbolAddress((void**)&X1b, g_X1b);
    cudaGetSymbolAddress((void**)&X2b, g_X2b);
    cudaGetSymbolAddress((void**)&Qp,  g_Q);
    cudaGetSymbolAddress((void**)&Kp,  g_K);
    cudaGetSymbolAddress((void**)&Wqt, g_Wqt);
    cudaGetSymbolAddress((void**)&Wkt, g_Wkt);
    cudaGetSymbolAddress((void**)&gnum, g_num);
    cudaGetSymbolAddress((void**)&gden, g_den);
    float* gnum1 = gnum + BATCH*SEQ;
    float* gden1 = gden + BATCH*SEQ;

    cudaFuncSetAttribute(gemm_bias_mma, cudaFuncAttributeMaxDynamicSharedMemorySize, P1_SMEM);
    cudaFuncSetAttribute(attn_mma,      cudaFuncAttributeMaxDynamicSharedMemorySize, P2_SMEM);

    const int nconv = (int)(((size_t)MTOT * DIM / 8) / 256);   // 6144 blocks
    convert_bf16_2<<<dim3(nconv, 1, 2), 256>>>(x1, x2, X1b, X2b);

    dim3 tgrid(DIM / 32, DIM / 32, 2);
    transpose_bf16_2<<<tgrid, dim3(32, 8)>>>(Wq, Wk, Wqt, Wkt);

    dim3 ggrid(DIM / 128, MTOT / 128, 2);   // (6, 128, 2) = 1536 CTAs
    gemm_bias_mma<<<ggrid, 256, P1_SMEM>>>(X1b, X2b, Wqt, Wkt, bq, bk, Qp, Kp);

    dim3 agrid(SEQ / 128, BATCH, 2);        // (16, 8, 2) = 256 CTAs
    attn_mma<<<agrid, 288, P2_SMEM>>>(Qp, Kp, gnum, gnum1, gden, gden1);

    finalize<<<BATCH*SEQ/256, 256>>>(gnum, gnum1, gden, gden1, out);
}

// round 16
// speedup vs baseline: 1.0611x; 1.0100x over previous
#include <cuda_runtime.h>
#include <cuda_bf16.h>
#include <cstdint>
#include <cstddef>

#define BATCH 8
#define SEQ   2048
#define DIM   768
#define MTOT  (BATCH*SEQ)   // 16384
#define NCH   12            // 768 / 64 k-chunks
#define TILE_BYTES 16384    // one (128-row x 64-k) bf16 tile, SW128-swizzled
#define NCONV ((MTOT*DIM/8)/256)   // 6144 convert blocks per operand
#define NTRANS ((DIM/32)*(DIM/32)) // 576 transpose blocks per operand

// ---------------- scratch (no dynamic allocation allowed) -------------------
__device__ __align__(256) __nv_bfloat16 g_X1b[(size_t)MTOT*DIM];
__device__ __align__(256) __nv_bfloat16 g_X2b[(size_t)MTOT*DIM];
__device__ __align__(256) __nv_bfloat16 g_Q  [(size_t)MTOT*DIM];
__device__ __align__(256) __nv_bfloat16 g_K  [(size_t)MTOT*DIM];
__device__ __align__(256) __nv_bfloat16 g_Wqt[(size_t)DIM*DIM];
__device__ __align__(256) __nv_bfloat16 g_Wkt[(size_t)DIM*DIM];
__device__ float    g_num[BATCH*SEQ];    // zero-init; reset by finisher each run
__device__ float    g_den[BATCH*SEQ];
__device__ uint32_t g_cnt[BATCH*16];     // ticket counters (parity across replays)

// ---------------- helpers ----------------------------------------------------
#define SWZ(o) ((o) ^ (((o) >> 3) & 0x70))

__device__ __forceinline__ uint32_t smem_u32(const void* p) {
    uint32_t a;
    asm("{ .reg .u64 t; cvta.to.shared.u64 t, %1; cvt.u32.u64 %0, t; }"
        : "=r"(a) : "l"(p));
    return a;
}
__device__ __forceinline__ void ldsm_x4(uint32_t* r, uint32_t addr) {
    asm volatile("ldmatrix.sync.aligned.m8n8.x4.shared.b16 {%0,%1,%2,%3}, [%4];"
                 : "=r"(r[0]), "=r"(r[1]), "=r"(r[2]), "=r"(r[3]) : "r"(addr));
}
__device__ __forceinline__ void mma_bf16(float* c, const uint32_t* a,
                                         uint32_t b0, uint32_t b1) {
    asm volatile(
        "mma.sync.aligned.m16n8k16.row.col.f32.bf16.bf16.f32 "
        "{%0,%1,%2,%3}, {%4,%5,%6,%7}, {%8,%9}, {%0,%1,%2,%3};"
        : "+f"(c[0]), "+f"(c[1]), "+f"(c[2]), "+f"(c[3])
        : "r"(a[0]), "r"(a[1]), "r"(a[2]), "r"(a[3]), "r"(b0), "r"(b1));
}
__device__ __forceinline__ float fast_tanh(float x) {
    float y; asm("tanh.approx.f32 %0, %1;" : "=f"(y) : "f"(x)); return y;
}

// mbarrier + bulk-copy primitives (Hopper+ PTX; valid on plain sm_103)
#define MBARRIER_INIT(addr, cnt) \
    asm volatile("mbarrier.init.shared.b64 [%0], %1;" :: "r"(addr), "r"(cnt) : "memory")
#define MBARRIER_EXPECT_TX(addr, bytes) \
    asm volatile("mbarrier.arrive.expect_tx.shared.b64 _, [%0], %1;" \
                 :: "r"(addr), "r"(bytes) : "memory")
#define MBARRIER_ARRIVE(addr) \
    asm volatile("mbarrier.arrive.release.cta.shared.b64 _, [%0];" \
                 :: "r"(addr) : "memory")
#define MBARRIER_WAIT_PARITY(mbar, par) do { \
    uint32_t _m = (uint32_t)(mbar), _p = (uint32_t)(par), _d; \
    asm volatile("{\n\t.reg .pred p;\n\t" \
        "mbarrier.try_wait.parity.acquire.cta.shared::cta.b64 p, [%1], %2;\n\t" \
        "selp.b32 %0, 1, 0, p;\n\t}" : "=r"(_d) : "r"(_m), "r"(_p) : "memory"); \
    if (!_d) { \
        asm volatile("{\n\t.reg .pred P1;\n\t" \
            "WL_%=:\n\t" \
            "mbarrier.try_wait.parity.acquire.cta.shared::cta.b64 P1, [%0], %1, 0x989680;\n\t" \
            "@P1 bra.uni WD_%=;\n\t" \
            "bra.uni WL_%=;\n\t" \
            "WD_%=:\n\t}" :: "r"(_m), "r"(_p) : "memory"); \
    } \
} while (0)
__device__ __forceinline__ void bulk_g2s(uint32_t dst, const void* src,
                                         uint32_t bytes, uint32_t mbar) {
    asm volatile(
        "cp.async.bulk.shared::cluster.global.mbarrier::complete_tx::bytes "
        "[%0], [%1], %2, [%3];"
        :: "r"(dst), "l"(src), "r"(bytes), "r"(mbar) : "memory");
}

// 128x128x64 chunk MMA (8 warps, 32x64 warp tiles), XOR-folded addressing.
#define CHUNK_MMA_SW(AsX, BsX) do { \
    const uint32_t _Ab0 = (AsX) + aswz0; \
    const uint32_t _Ab1 = (AsX) + aswz1; \
    const uint32_t _Bb  = (BsX) + bswz0; \
    _Pragma("unroll") \
    for (int ks = 0; ks < 4; ks++) { \
        const uint32_t _kx = ks * 32; \
        uint32_t a0[4], a1[4], bmA[4], bmB[4]; \
        ldsm_x4(a0,  _Ab0 ^ _kx); \
        ldsm_x4(a1,  _Ab1 ^ _kx); \
        ldsm_x4(bmA, _Bb ^ _kx); \
        _Pragma("unroll") \
        for (int np = 0; np < 4; np++) { \
            uint32_t* bc = (np & 1) ? bmB : bmA; \
            uint32_t* bn_ = (np & 1) ? bmA : bmB; \
            if (np < 3) \
                ldsm_x4(bn_, (_Bb + (np + 1) * 2048) ^ _kx); \
            mma_bf16(acc[0][np*2],   a0, bc[0], bc[2]); \
            mma_bf16(acc[0][np*2+1], a0, bc[1], bc[3]); \
            mma_bf16(acc[1][np*2],   a1, bc[0], bc[2]); \
            mma_bf16(acc[1][np*2+1], a1, bc[1], bc[3]); \
        } \
    } \
} while (0)

// ---------------------------------------------------------------------------
// prep: merged convert (f32 -> bf16 blocked SW128) + transpose (W -> Wt blocked)
// blocks [0, NCONV): convert; blocks [NCONV, NCONV+NTRANS): transpose.
// blockIdx.z selects operand pair.
// ---------------------------------------------------------------------------
__global__ void __launch_bounds__(256)
prep(const float* __restrict__ x1, const float* __restrict__ x2,
     const float* __restrict__ Wq, const float* __restrict__ Wk,
     __nv_bfloat16* __restrict__ X1b, __nv_bfloat16* __restrict__ X2b,
     __nv_bfloat16* __restrict__ Wqt, __nv_bfloat16* __restrict__ Wkt)
{
    __shared__ float t[32][33];
    const int tid = threadIdx.x;
    if (blockIdx.x < NCONV) {
        const float* x = blockIdx.z ? x2 : x1;
        char* y = (char*)(blockIdx.z ? X2b : X1b);
        const size_t i = ((size_t)blockIdx.x * 256 + tid) * 8;
        const uint32_t m = (uint32_t)(i / DIM), k = (uint32_t)(i % DIM);
        float4 v0 = *(const float4*)(x + i);
        float4 v1 = *(const float4*)(x + i + 4);
        __nv_bfloat162 a = __floats2bfloat162_rn(v0.x, v0.y);
        __nv_bfloat162 b = __floats2bfloat162_rn(v0.z, v0.w);
        __nv_bfloat162 c = __floats2bfloat162_rn(v1.x, v1.y);
        __nv_bfloat162 d = __floats2bfloat162_rn(v1.z, v1.w);
        uint4 st; st.x = *(uint32_t*)&a; st.y = *(uint32_t*)&b;
        st.z = *(uint32_t*)&c; st.w = *(uint32_t*)&d;
        const size_t tbase = ((size_t)(m >> 7) * NCH + (k >> 6)) << 14;
        *(uint4*)(y + tbase + SWZ((m & 127) * 128 + (k & 63) * 2)) = st;
    } else {
        const float* W = blockIdx.z ? Wk : Wq;
        char* Wt = (char*)(blockIdx.z ? Wkt : Wqt);
        const int bidx = blockIdx.x - NCONV;
        const int bn = (bidx % (DIM / 32)) * 32, bk = (bidx / (DIM / 32)) * 32;
        const int tx = tid & 31, ty = tid >> 5;
#pragma unroll
        for (int j = 0; j < 4; j++)
            t[ty + j * 8][tx] = W[(size_t)(bk + ty + j * 8) * DIM + bn + tx];
        __syncthreads();
#pragma unroll
        for (int j = 0; j < 4; j++) {
            const uint32_t n = bn + ty + j * 8, k = bk + tx;
            const size_t tbase = ((size_t)(n >> 7) * NCH + (k >> 6)) << 14;
            *(__nv_bfloat16*)(Wt + tbase + SWZ((n & 127) * 128 + (k & 63) * 2)) =
                __float2bfloat16(t[tx][ty + j * 8]);
        }
    }
}

// ---------------------------------------------------------------------------
// Phase 1 (merged Q & K via blockIdx.z): blocked-tile GEMM, bulk-copy loads.
// Ring-3 slots with full/empty mbarrier pairs (R13, proven). Unchanged.
// ---------------------------------------------------------------------------
#define P1_SMEM (1024 + 6*TILE_BYTES + 512)

__global__ void __launch_bounds__(256, 2)
gemm_bias_mma(const __nv_bfloat16* __restrict__ A1, const __nv_bfloat16* __restrict__ A2,
              const __nv_bfloat16* __restrict__ B1, const __nv_bfloat16* __restrict__ B2,
              const float* __restrict__ bias1, const float* __restrict__ bias2,
              __nv_bfloat16* __restrict__ O1, __nv_bfloat16* __restrict__ O2)
{
    extern __shared__ __align__(16) char smem[];
    const uint32_t sb = smem_u32(smem);
    const int tid = threadIdx.x, lane = tid & 31, wid = tid >> 5;
    const int wm = wid >> 1, wn = wid & 1;
    const int n0 = blockIdx.x * 128, m0 = blockIdx.y * 128;
    const int z = blockIdx.z;

    const char* A  = (const char*)(z ? A2 : A1);
    const char* Bt = (const char*)(z ? B2 : B1);
    const float* bias = z ? bias2 : bias1;
    char* Out = (char*)(z ? O2 : O1);

    const uint32_t MBF = sb + 8, MBE = sb + 32;
    float* bias_s = (float*)(smem + 1024 + 6*TILE_BYTES);
    if (tid == 0) {
        MBARRIER_INIT(MBF + 0, 1);   MBARRIER_INIT(MBF + 8, 1);   MBARRIER_INIT(MBF + 16, 1);
        MBARRIER_INIT(MBE + 0, 256); MBARRIER_INIT(MBE + 8, 256); MBARRIER_INIT(MBE + 16, 256);
    }
    if (tid < 128) bias_s[tid] = bias[n0 + tid];
    __syncthreads();

    const uint32_t seg = (uint32_t)(lane >> 4) * 16;
    const uint32_t aoffp0 = (uint32_t)(wm * 32 + (lane & 15)) * 128 + seg;
    const uint32_t aswz0 = SWZ(aoffp0);
    const uint32_t aswz1 = SWZ(aoffp0 + 16 * 128);
    const uint32_t bswz0 = SWZ((uint32_t)(wn * 64 + (lane & 15)) * 128 + seg);

#define ASLOT(s) (sb + 1024 + (s) * TILE_BYTES)
#define BSLOT(s) (sb + 1024 + 3*TILE_BYTES + (s) * TILE_BYTES)
#define GISSUE(cc, S) do { \
        MBARRIER_EXPECT_TX(MBF + 8 * (S), 2 * TILE_BYTES); \
        bulk_g2s(ASLOT(S), A  + (((size_t)(m0 >> 7) * NCH + (cc)) << 14), \
                 TILE_BYTES, MBF + 8 * (S)); \
        bulk_g2s(BSLOT(S), Bt + (((size_t)(n0 >> 7) * NCH + (cc)) << 14), \
                 TILE_BYTES, MBF + 8 * (S)); \
    } while (0)

    float acc[2][8][4];
#pragma unroll
    for (int i = 0; i < 2; i++)
#pragma unroll
        for (int j = 0; j < 8; j++)
#pragma unroll
            for (int q = 0; q < 4; q++) acc[i][j][q] = 0.f;

    if (tid == 0) { GISSUE(0, 0); GISSUE(1, 1); GISSUE(2, 2); }

    int phf0 = 0, phf1 = 0, phf2 = 0;
    int phe0 = 0, phe1 = 0, phe2 = 0;

#define GBODY(cc, S, PHF, PHE) do { \
        MBARRIER_WAIT_PARITY(MBF + 8 * (S), PHF); PHF ^= 1; \
        CHUNK_MMA_SW(ASLOT(S), BSLOT(S)); \
        MBARRIER_ARRIVE(MBE + 8 * (S)); \
        if ((cc) + 3 < NCH && tid == 0) { \
            MBARRIER_WAIT_PARITY(MBE + 8 * (S), PHE); PHE ^= 1; \
            GISSUE((cc) + 3, S); \
        } \
    } while (0)

#pragma unroll
    for (int c0 = 0; c0 < NCH; c0 += 3) {
        GBODY(c0,     0, phf0, phe0);
        GBODY(c0 + 1, 1, phf1, phe1);
        GBODY(c0 + 2, 2, phf2, phe2);
    }
#undef GBODY
#undef GISSUE
#undef ASLOT
#undef BSLOT

#pragma unroll
    for (int mt = 0; mt < 2; mt++) {
        const uint32_t row0 = (uint32_t)(wm * 32 + mt * 16 + (lane >> 2));
#pragma unroll
        for (int nt = 0; nt < 8; nt++) {
            const int nl = wn * 64 + nt * 8 + (lane & 3) * 2;
            const float b0 = bias_s[nl], b1 = bias_s[nl + 1];
            __nv_bfloat162 p0 = __floats2bfloat162_rn(acc[mt][nt][0] + b0, acc[mt][nt][1] + b1);
            __nv_bfloat162 p1 = __floats2bfloat162_rn(acc[mt][nt][2] + b0, acc[mt][nt][3] + b1);
            const size_t tb = ((size_t)(m0 >> 7) * NCH + (n0 >> 6) + wn) << 14;
            const uint32_t col2 = (uint32_t)(nt * 8 + (lane & 3) * 2) * 2;
            *(uint32_t*)(Out + tb + SWZ(row0 * 128 + col2))       = *(uint32_t*)&p0;
            *(uint32_t*)(Out + tb + SWZ((row0 + 8) * 128 + col2)) = *(uint32_t*)&p1;
        }
    }
}

// ---------------------------------------------------------------------------
// Phase 2 (R13 structure + fused finalize): per (t-block, batch, s-half),
// ring-3 full/empty mbarrier pipeline; partials atomicAdd into g_num/g_den;
// ticket counter elects the second CTA of each pair to finalize + reset.
// SMEM: [8) full x3 | [32) empty x3 | [48) ticket | [64) num | [576) den | [2048) rings
// ---------------------------------------------------------------------------
#define P2_SMEM (2048 + 6*TILE_BYTES)
#define GTOT (8*NCH)   // 96

__global__ void __launch_bounds__(256, 2)
attn_mma(const __nv_bfloat16* __restrict__ Q, const __nv_bfloat16* __restrict__ K,
         float* __restrict__ gnum, float* __restrict__ gden,
         uint32_t* __restrict__ gcnt, float* __restrict__ out)
{
    extern __shared__ __align__(16) char smem[];
    const uint32_t sb = smem_u32(smem);
    float* num_sh = (float*)(smem + 64);
    float* den_sh = (float*)(smem + 576);
    uint32_t* ticket_sh = (uint32_t*)(smem + 48);
    const int tid = threadIdx.x, lane = tid & 31, wid = tid >> 5;
    const int wm = wid >> 1, wn = wid & 1;
    const int t0 = blockIdx.x * 128, b = blockIdx.y, sh = blockIdx.z;
    const uint32_t MBF = sb + 8, MBE = sb + 32;

    const char* Qb = (const char*)Q;
    const char* Kb = (const char*)K;
    const int ktile = b * 16 + blockIdx.x;
    const int qtile0 = b * 16 + sh * 8;

    if (tid == 0) {
        MBARRIER_INIT(MBF + 0, 1);   MBARRIER_INIT(MBF + 8, 1);   MBARRIER_INIT(MBF + 16, 1);
        MBARRIER_INIT(MBE + 0, 256); MBARRIER_INIT(MBE + 8, 256); MBARRIER_INIT(MBE + 16, 256);
    }
    if (tid < 128) { num_sh[tid] = 0.f; den_sh[tid] = 0.f; }
    __syncthreads();

    const uint32_t seg = (uint32_t)(lane >> 4) * 16;
    const uint32_t aoffp0 = (uint32_t)(wm * 32 + (lane & 15)) * 128 + seg;
    const uint32_t aswz0 = SWZ(aoffp0);
    const uint32_t aswz1 = SWZ(aoffp0 + 16 * 128);
    const uint32_t bswz0 = SWZ((uint32_t)(wn * 64 + (lane & 15)) * 128 + seg);

#define QSLOT(s) (sb + 2048 + (s) * TILE_BYTES)
#define KSLOT(s) (sb + 2048 + 3*TILE_BYTES + (s) * TILE_BYTES)
#define AISSUE(gg, S) do { \
        const int _st = (gg) / NCH, _cc = (gg) % NCH; \
        MBARRIER_EXPECT_TX(MBF + 8 * (S), 2 * TILE_BYTES); \
        bulk_g2s(QSLOT(S), Qb + (((size_t)(qtile0 + _st) * NCH + _cc) << 14), \
                 TILE_BYTES, MBF + 8 * (S)); \
        bulk_g2s(KSLOT(S), Kb + (((size_t)ktile * NCH + _cc) << 14), \
                 TILE_BYTES, MBF + 8 * (S)); \
    } while (0)

#define EPI() do { \
        _Pragma("unroll") \
        for (int nt = 0; nt < 8; nt++) { \
            float vn0 = 0.f, vn1 = 0.f, vd0 = 0.f, vd1 = 0.f; \
            _Pragma("unroll") \
            for (int mt = 0; mt < 2; mt++) { \
                const float q0 = acc[mt][nt][0], q1 = acc[mt][nt][1]; \
                const float q2 = acc[mt][nt][2], q3 = acc[mt][nt][3]; \
                const float e0 = __expf(fast_tanh(q0)); \
                const float e1 = __expf(fast_tanh(q1)); \
                const float e2 = __expf(fast_tanh(q2)); \
                const float e3 = __expf(fast_tanh(q3)); \
                vn0 += e0 * q0 + e2 * q2;  vd0 += e0 + e2; \
                vn1 += e1 * q1 + e3 * q3;  vd1 += e1 + e3; \
            } \
            _Pragma("unroll") \
            for (int o = 4; o <= 16; o <<= 1) { \
                vn0 += __shfl_xor_sync(0xFFFFFFFFu, vn0, o); \
                vn1 += __shfl_xor_sync(0xFFFFFFFFu, vn1, o); \
                vd0 += __shfl_xor_sync(0xFFFFFFFFu, vd0, o); \
                vd1 += __shfl_xor_sync(0xFFFFFFFFu, vd1, o); \
            } \
            if (lane < 4) { \
                const int col = wn * 64 + nt * 8 + lane * 2; \
                atomicAdd(&num_sh[col],     vn0); \
                atomicAdd(&num_sh[col + 1], vn1); \
                atomicAdd(&den_sh[col],     vd0); \
                atomicAdd(&den_sh[col + 1], vd1); \
            } \
        } \
        _Pragma("unroll") \
        for (int i = 0; i < 2; i++) \
            _Pragma("unroll") \
            for (int j = 0; j < 8; j++) \
                _Pragma("unroll") \
                for (int q = 0; q < 4; q++) acc[i][j][q] = 0.f; \
    } while (0)

    float acc[2][8][4];
#pragma unroll
    for (int i = 0; i < 2; i++)
#pragma unroll
        for (int j = 0; j < 8; j++)
#pragma unroll
            for (int q = 0; q < 4; q++) acc[i][j][q] = 0.f;

    if (tid == 0) { AISSUE(0, 0); AISSUE(1, 1); AISSUE(2, 2); }

    int phf0 = 0, phf1 = 0, phf2 = 0;
    int phe0 = 0, phe1 = 0, phe2 = 0;

#define ABODY(gg, S, PHF, PHE, DO_EPI) do { \
        MBARRIER_WAIT_PARITY(MBF + 8 * (S), PHF); PHF ^= 1; \
        CHUNK_MMA_SW(QSLOT(S), KSLOT(S)); \
        MBARRIER_ARRIVE(MBE + 8 * (S)); \
        if (DO_EPI) EPI(); \
        if ((gg) + 3 < GTOT && tid == 0) { \
            MBARRIER_WAIT_PARITY(MBE + 8 * (S), PHE); PHE ^= 1; \
            AISSUE((gg) + 3, S); \
        } \
    } while (0)

    for (int g0 = 0; g0 < GTOT; g0 += 3) {
        ABODY(g0,     0, phf0, phe0, false);
        ABODY(g0 + 1, 1, phf1, phe1, false);
        // tiles are 12 chunks; tile-final chunk lands at slot 2 when g0%12==9
        ABODY(g0 + 2, 2, phf2, phe2, (g0 % NCH) == 9);
    }
#undef ABODY
#undef AISSUE
#undef QSLOT
#undef KSLOT
#undef EPI

    __syncthreads();
    // publish partials
    if (tid < 128) {
        atomicAdd(&gnum[(size_t)b * SEQ + t0 + tid], num_sh[tid]);
        atomicAdd(&gden[(size_t)b * SEQ + t0 + tid], den_sh[tid]);
    }
    __threadfence();   // release partials before taking a ticket
    __syncthreads();
    if (tid == 0) ticket_sh[0] = atomicAdd(&gcnt[b * 16 + blockIdx.x], 1u);
    __syncthreads();
    if (ticket_sh[0] & 1u) {
        // second CTA of the pair: both partials are visible; finalize + reset
        __threadfence();   // acquire
        if (tid < 128) {
            const size_t idx = (size_t)b * SEQ + t0 + tid;
            const float n = gnum[idx], d = gden[idx];
            out[idx] = n / (d + 1e-7f);
            gnum[idx] = 0.f;   // reset for next graph replay
            gden[idx] = 0.f;
        }
    }
}

// ---------------------------------------------------------------------------
extern "C" void kernel_launch(void* const* d_in, const int* in_sizes, int n_in,
                              void* d_out, int out_size)
{
    const float* x1 = (const float*)d_in[0];
    const float* x2 = (const float*)d_in[1];
    const float* Wq = (const float*)d_in[2];
    const float* bq = (const float*)d_in[3];
    const float* Wk = (const float*)d_in[4];
    const float* bk = (const float*)d_in[5];
    float* out = (float*)d_out;

    __nv_bfloat16 *X1b, *X2b, *Qp, *Kp, *Wqt, *Wkt;
    float *gnum, *gden;
    uint32_t* gcnt;
    cudaGetSymbolAddress((void**)&X1b, g_X1b);
    cudaGetSymbolAddress((void**)&X2b, g_X2b);
    cudaGetSymbolAddress((void**)&Qp,  g_Q);
    cudaGetSymbolAddress((void**)&Kp,  g_K);
    cudaGetSymbolAddress((void**)&Wqt, g_Wqt);
    cudaGetSymbolAddress((void**)&Wkt, g_Wkt);
    cudaGetSymbolAddress((void**)&gnum, g_num);
    cudaGetSymbolAddress((void**)&gden, g_den);
    cudaGetSymbolAddress((void**)&gcnt, g_cnt);

    cudaFuncSetAttribute(gemm_bias_mma, cudaFuncAttributeMaxDynamicSharedMemorySize, P1_SMEM);
    cudaFuncSetAttribute(attn_mma,      cudaFuncAttributeMaxDynamicSharedMemorySize, P2_SMEM);

    prep<<<dim3(NCONV + NTRANS, 1, 2), 256>>>(x1, x2, Wq, Wk, X1b, X2b, Wqt, Wkt);

    dim3 ggrid(DIM / 128, MTOT / 128, 2);   // (6, 128, 2) = 1536 CTAs
    gemm_bias_mma<<<ggrid, 256, P1_SMEM>>>(X1b, X2b, Wqt, Wkt, bq, bk, Qp, Kp);

    dim3 agrid(SEQ / 128, BATCH, 2);        // (16, 8, 2) = 256 CTAs
    attn_mma<<<agrid, 256, P2_SMEM>>>(Qp, Kp, gnum, gden, gcnt, out);
}

// round 17
// speedup vs baseline: 1.0668x; 1.0053x over previous
#include <cuda_runtime.h>
#include <cuda_bf16.h>
#include <cstdint>
#include <cstddef>

#define BATCH 8
#define SEQ   2048
#define DIM   768
#define MTOT  (BATCH*SEQ)   // 16384
#define NCH   12            // 768 / 64 k-chunks
#define TILE_BYTES 16384    // one (128-row x 64-k) bf16 tile, SW128-swizzled
#define NCONV ((MTOT*DIM/8)/256)   // 6144 convert blocks per operand
#define NTRANS ((DIM/32)*(DIM/32)) // 576 transpose blocks per operand

// ---------------- scratch (no dynamic allocation allowed) -------------------
__device__ __align__(256) __nv_bfloat16 g_X1b[(size_t)MTOT*DIM];
__device__ __align__(256) __nv_bfloat16 g_X2b[(size_t)MTOT*DIM];
__device__ __align__(256) __nv_bfloat16 g_Q  [(size_t)MTOT*DIM];
__device__ __align__(256) __nv_bfloat16 g_K  [(size_t)MTOT*DIM];
__device__ __align__(256) __nv_bfloat16 g_Wqt[(size_t)DIM*DIM];
__device__ __align__(256) __nv_bfloat16 g_Wkt[(size_t)DIM*DIM];
__device__ float    g_num[BATCH*SEQ];    // zero-init; reset by finisher each run
__device__ float    g_den[BATCH*SEQ];
__device__ uint32_t g_cnt[BATCH*16];     // ticket counters (parity across replays)

// ---------------- helpers ----------------------------------------------------
#define SWZ(o) ((o) ^ (((o) >> 3) & 0x70))

__device__ __forceinline__ uint32_t smem_u32(const void* p) {
    uint32_t a;
    asm("{ .reg .u64 t; cvta.to.shared.u64 t, %1; cvt.u32.u64 %0, t; }"
        : "=r"(a) : "l"(p));
    return a;
}
__device__ __forceinline__ void ldsm_x4(uint32_t* r, uint32_t addr) {
    asm volatile("ldmatrix.sync.aligned.m8n8.x4.shared.b16 {%0,%1,%2,%3}, [%4];"
                 : "=r"(r[0]), "=r"(r[1]), "=r"(r[2]), "=r"(r[3]) : "r"(addr));
}
__device__ __forceinline__ void mma_bf16(float* c, const uint32_t* a,
                                         uint32_t b0, uint32_t b1) {
    asm volatile(
        "mma.sync.aligned.m16n8k16.row.col.f32.bf16.bf16.f32 "
        "{%0,%1,%2,%3}, {%4,%5,%6,%7}, {%8,%9}, {%0,%1,%2,%3};"
        : "+f"(c[0]), "+f"(c[1]), "+f"(c[2]), "+f"(c[3])
        : "r"(a[0]), "r"(a[1]), "r"(a[2]), "r"(a[3]), "r"(b0), "r"(b1));
}
__device__ __forceinline__ float fast_tanh(float x) {
    float y; asm("tanh.approx.f32 %0, %1;" : "=f"(y) : "f"(x)); return y;
}

// mbarrier + bulk-copy primitives (Hopper+ PTX; valid on plain sm_103)
#define MBARRIER_INIT(addr, cnt) \
    asm volatile("mbarrier.init.shared.b64 [%0], %1;" :: "r"(addr), "r"(cnt) : "memory")
#define MBARRIER_EXPECT_TX(addr, bytes) \
    asm volatile("mbarrier.arrive.expect_tx.shared.b64 _, [%0], %1;" \
                 :: "r"(addr), "r"(bytes) : "memory")
#define MBARRIER_ARRIVE(addr) \
    asm volatile("mbarrier.arrive.release.cta.shared.b64 _, [%0];" \
                 :: "r"(addr) : "memory")
#define MBARRIER_WAIT_PARITY(mbar, par) do { \
    uint32_t _m = (uint32_t)(mbar), _p = (uint32_t)(par), _d; \
    asm volatile("{\n\t.reg .pred p;\n\t" \
        "mbarrier.try_wait.parity.acquire.cta.shared::cta.b64 p, [%1], %2;\n\t" \
        "selp.b32 %0, 1, 0, p;\n\t}" : "=r"(_d) : "r"(_m), "r"(_p) : "memory"); \
    if (!_d) { \
        asm volatile("{\n\t.reg .pred P1;\n\t" \
            "WL_%=:\n\t" \
            "mbarrier.try_wait.parity.acquire.cta.shared::cta.b64 P1, [%0], %1, 0x989680;\n\t" \
            "@P1 bra.uni WD_%=;\n\t" \
            "bra.uni WL_%=;\n\t" \
            "WD_%=:\n\t}" :: "r"(_m), "r"(_p) : "memory"); \
    } \
} while (0)
__device__ __forceinline__ void bulk_g2s(uint32_t dst, const void* src,
                                         uint32_t bytes, uint32_t mbar) {
    asm volatile(
        "cp.async.bulk.shared::cluster.global.mbarrier::complete_tx::bytes "
        "[%0], [%1], %2, [%3];"
        :: "r"(dst), "l"(src), "r"(bytes), "r"(mbar) : "memory");
}
__device__ __forceinline__ void bulk_s2g(void* dst, uint32_t src, uint32_t bytes) {
    asm volatile("cp.async.bulk.global.shared::cta.bulk_group [%0], [%1], %2;"
                 :: "l"(dst), "r"(src), "r"(bytes) : "memory");
}
#define BULK_COMMIT() asm volatile("cp.async.bulk.commit_group;" ::: "memory")
#define BULK_WAIT0()  asm volatile("cp.async.bulk.wait_group 0;" ::: "memory")
#define FENCE_ASYNC_S() asm volatile("fence.proxy.async.shared::cta;" ::: "memory")

// 128x128x64 chunk MMA (8 warps, 32x64 warp tiles), XOR-folded addressing.
#define CHUNK_MMA_SW(AsX, BsX) do { \
    const uint32_t _Ab0 = (AsX) + aswz0; \
    const uint32_t _Ab1 = (AsX) + aswz1; \
    const uint32_t _Bb  = (BsX) + bswz0; \
    _Pragma("unroll") \
    for (int ks = 0; ks < 4; ks++) { \
        const uint32_t _kx = ks * 32; \
        uint32_t a0[4], a1[4], bmA[4], bmB[4]; \
        ldsm_x4(a0,  _Ab0 ^ _kx); \
        ldsm_x4(a1,  _Ab1 ^ _kx); \
        ldsm_x4(bmA, _Bb ^ _kx); \
        _Pragma("unroll") \
        for (int np = 0; np < 4; np++) { \
            uint32_t* bc = (np & 1) ? bmB : bmA; \
            uint32_t* bn_ = (np & 1) ? bmA : bmB; \
            if (np < 3) \
                ldsm_x4(bn_, (_Bb + (np + 1) * 2048) ^ _kx); \
            mma_bf16(acc[0][np*2],   a0, bc[0], bc[2]); \
            mma_bf16(acc[0][np*2+1], a0, bc[1], bc[3]); \
            mma_bf16(acc[1][np*2],   a1, bc[0], bc[2]); \
            mma_bf16(acc[1][np*2+1], a1, bc[1], bc[3]); \
        } \
    } \
} while (0)

// ---------------------------------------------------------------------------
// prep: merged convert (f32 -> bf16 blocked SW128) + transpose (W -> Wt blocked)
// ---------------------------------------------------------------------------
__global__ void __launch_bounds__(256)
prep(const float* __restrict__ x1, const float* __restrict__ x2,
     const float* __restrict__ Wq, const float* __restrict__ Wk,
     __nv_bfloat16* __restrict__ X1b, __nv_bfloat16* __restrict__ X2b,
     __nv_bfloat16* __restrict__ Wqt, __nv_bfloat16* __restrict__ Wkt)
{
    __shared__ float t[32][33];
    const int tid = threadIdx.x;
    if (blockIdx.x < NCONV) {
        const float* x = blockIdx.z ? x2 : x1;
        char* y = (char*)(blockIdx.z ? X2b : X1b);
        const size_t i = ((size_t)blockIdx.x * 256 + tid) * 8;
        const uint32_t m = (uint32_t)(i / DIM), k = (uint32_t)(i % DIM);
        float4 v0 = *(const float4*)(x + i);
        float4 v1 = *(const float4*)(x + i + 4);
        __nv_bfloat162 a = __floats2bfloat162_rn(v0.x, v0.y);
        __nv_bfloat162 b = __floats2bfloat162_rn(v0.z, v0.w);
        __nv_bfloat162 c = __floats2bfloat162_rn(v1.x, v1.y);
        __nv_bfloat162 d = __floats2bfloat162_rn(v1.z, v1.w);
        uint4 st; st.x = *(uint32_t*)&a; st.y = *(uint32_t*)&b;
        st.z = *(uint32_t*)&c; st.w = *(uint32_t*)&d;
        const size_t tbase = ((size_t)(m >> 7) * NCH + (k >> 6)) << 14;
        *(uint4*)(y + tbase + SWZ((m & 127) * 128 + (k & 63) * 2)) = st;
    } else {
        const float* W = blockIdx.z ? Wk : Wq;
        char* Wt = (char*)(blockIdx.z ? Wkt : Wqt);
        const int bidx = blockIdx.x - NCONV;
        const int bn = (bidx % (DIM / 32)) * 32, bk = (bidx / (DIM / 32)) * 32;
        const int tx = tid & 31, ty = tid >> 5;
#pragma unroll
        for (int j = 0; j < 4; j++)
            t[ty + j * 8][tx] = W[(size_t)(bk + ty + j * 8) * DIM + bn + tx];
        __syncthreads();
#pragma unroll
        for (int j = 0; j < 4; j++) {
            const uint32_t n = bn + ty + j * 8, k = bk + tx;
            const size_t tbase = ((size_t)(n >> 7) * NCH + (k >> 6)) << 14;
            *(__nv_bfloat16*)(Wt + tbase + SWZ((n & 127) * 128 + (k & 63) * 2)) =
                __float2bfloat16(t[tx][ty + j * 8]);
        }
    }
}

// ---------------------------------------------------------------------------
// Phase 1 (merged Q & K via blockIdx.z): blocked-tile GEMM, bulk-copy loads.
// Ring-3 full/empty mbarrier pipeline (R13). NEW: epilogue stages output tiles
// in the drained A-ring slots and issues 2x 16KB bulk S2G stores (no scattered STG).
// ---------------------------------------------------------------------------
#define P1_SMEM (1024 + 6*TILE_BYTES + 512)

__global__ void __launch_bounds__(256, 2)
gemm_bias_mma(const __nv_bfloat16* __restrict__ A1, const __nv_bfloat16* __restrict__ A2,
              const __nv_bfloat16* __restrict__ B1, const __nv_bfloat16* __restrict__ B2,
              const float* __restrict__ bias1, const float* __restrict__ bias2,
              __nv_bfloat16* __restrict__ O1, __nv_bfloat16* __restrict__ O2)
{
    extern __shared__ __align__(16) char smem[];
    const uint32_t sb = smem_u32(smem);
    const int tid = threadIdx.x, lane = tid & 31, wid = tid >> 5;
    const int wm = wid >> 1, wn = wid & 1;
    const int n0 = blockIdx.x * 128, m0 = blockIdx.y * 128;
    const int z = blockIdx.z;

    const char* A  = (const char*)(z ? A2 : A1);
    const char* Bt = (const char*)(z ? B2 : B1);
    const float* bias = z ? bias2 : bias1;
    char* Out = (char*)(z ? O2 : O1);

    const uint32_t MBF = sb + 8, MBE = sb + 32;
    float* bias_s = (float*)(smem + 1024 + 6*TILE_BYTES);
    if (tid == 0) {
        MBARRIER_INIT(MBF + 0, 1);   MBARRIER_INIT(MBF + 8, 1);   MBARRIER_INIT(MBF + 16, 1);
        MBARRIER_INIT(MBE + 0, 256); MBARRIER_INIT(MBE + 8, 256); MBARRIER_INIT(MBE + 16, 256);
    }
    if (tid < 128) bias_s[tid] = bias[n0 + tid];
    __syncthreads();

    const uint32_t seg = (uint32_t)(lane >> 4) * 16;
    const uint32_t aoffp0 = (uint32_t)(wm * 32 + (lane & 15)) * 128 + seg;
    const uint32_t aswz0 = SWZ(aoffp0);
    const uint32_t aswz1 = SWZ(aoffp0 + 16 * 128);
    const uint32_t bswz0 = SWZ((uint32_t)(wn * 64 + (lane & 15)) * 128 + seg);

#define ASLOT(s) (sb + 1024 + (s) * TILE_BYTES)
#define BSLOT(s) (sb + 1024 + 3*TILE_BYTES + (s) * TILE_BYTES)
#define GISSUE(cc, S) do { \
        MBARRIER_EXPECT_TX(MBF + 8 * (S), 2 * TILE_BYTES); \
        bulk_g2s(ASLOT(S), A  + (((size_t)(m0 >> 7) * NCH + (cc)) << 14), \
                 TILE_BYTES, MBF + 8 * (S)); \
        bulk_g2s(BSLOT(S), Bt + (((size_t)(n0 >> 7) * NCH + (cc)) << 14), \
                 TILE_BYTES, MBF + 8 * (S)); \
    } while (0)

    float acc[2][8][4];
#pragma unroll
    for (int i = 0; i < 2; i++)
#pragma unroll
        for (int j = 0; j < 8; j++)
#pragma unroll
            for (int q = 0; q < 4; q++) acc[i][j][q] = 0.f;

    if (tid == 0) { GISSUE(0, 0); GISSUE(1, 1); GISSUE(2, 2); }

    int phf0 = 0, phf1 = 0, phf2 = 0;
    int phe0 = 0, phe1 = 0, phe2 = 0;

#define GBODY(cc, S, PHF, PHE) do { \
        MBARRIER_WAIT_PARITY(MBF + 8 * (S), PHF); PHF ^= 1; \
        CHUNK_MMA_SW(ASLOT(S), BSLOT(S)); \
        MBARRIER_ARRIVE(MBE + 8 * (S)); \
        if ((cc) + 3 < NCH && tid == 0) { \
            MBARRIER_WAIT_PARITY(MBE + 8 * (S), PHE); PHE ^= 1; \
            GISSUE((cc) + 3, S); \
        } \
    } while (0)

#pragma unroll
    for (int c0 = 0; c0 < NCH; c0 += 3) {
        GBODY(c0,     0, phf0, phe0);
        GBODY(c0 + 1, 1, phf1, phe1);
        GBODY(c0 + 2, 2, phf2, phe2);
    }
#undef GBODY
#undef GISSUE

    // ---- epilogue: stage (acc + bias) into drained A-ring slots, bulk S2G ----
    __syncthreads();   // all warps done reading slots
#pragma unroll
    for (int mt = 0; mt < 2; mt++) {
        const uint32_t row0 = (uint32_t)(wm * 32 + mt * 16 + (lane >> 2));
#pragma unroll
        for (int nt = 0; nt < 8; nt++) {
            const int nl = wn * 64 + nt * 8 + (lane & 3) * 2;
            const float b0 = bias_s[nl], b1 = bias_s[nl + 1];
            __nv_bfloat162 p0 = __floats2bfloat162_rn(acc[mt][nt][0] + b0, acc[mt][nt][1] + b1);
            __nv_bfloat162 p1 = __floats2bfloat162_rn(acc[mt][nt][2] + b0, acc[mt][nt][3] + b1);
            const uint32_t col2 = (uint32_t)(nt * 8 + (lane & 3) * 2) * 2;
            char* stg = smem + 1024 + wn * TILE_BYTES;   // ASLOT(wn) as staging
            *(uint32_t*)(stg + SWZ(row0 * 128 + col2))       = *(uint32_t*)&p0;
            *(uint32_t*)(stg + SWZ((row0 + 8) * 128 + col2)) = *(uint32_t*)&p1;
        }
    }
    FENCE_ASYNC_S();
    __syncthreads();
    if (tid == 0) {
        const size_t tb0 = ((size_t)(m0 >> 7) * NCH + (n0 >> 6)) << 14;
        bulk_s2g(Out + tb0,              ASLOT(0), TILE_BYTES);
        bulk_s2g(Out + tb0 + TILE_BYTES, ASLOT(1), TILE_BYTES);
        BULK_COMMIT();
        BULK_WAIT0();
    }
#undef ASLOT
#undef BSLOT
}

// ---------------------------------------------------------------------------
// Phase 2 (R16, unchanged): ring-3 full/empty pipeline + fused finalize.
// ---------------------------------------------------------------------------
#define P2_SMEM (2048 + 6*TILE_BYTES)
#define GTOT (8*NCH)   // 96

__global__ void __launch_bounds__(256, 2)
attn_mma(const __nv_bfloat16* __restrict__ Q, const __nv_bfloat16* __restrict__ K,
         float* __restrict__ gnum, float* __restrict__ gden,
         uint32_t* __restrict__ gcnt, float* __restrict__ out)
{
    extern __shared__ __align__(16) char smem[];
    const uint32_t sb = smem_u32(smem);
    float* num_sh = (float*)(smem + 64);
    float* den_sh = (float*)(smem + 576);
    uint32_t* ticket_sh = (uint32_t*)(smem + 48);
    const int tid = threadIdx.x, lane = tid & 31, wid = tid >> 5;
    const int wm = wid >> 1, wn = wid & 1;
    const int t0 = blockIdx.x * 128, b = blockIdx.y, sh = blockIdx.z;
    const uint32_t MBF = sb + 8, MBE = sb + 32;

    const char* Qb = (const char*)Q;
    const char* Kb = (const char*)K;
    const int ktile = b * 16 + blockIdx.x;
    const int qtile0 = b * 16 + sh * 8;

    if (tid == 0) {
        MBARRIER_INIT(MBF + 0, 1);   MBARRIER_INIT(MBF + 8, 1);   MBARRIER_INIT(MBF + 16, 1);
        MBARRIER_INIT(MBE + 0, 256); MBARRIER_INIT(MBE + 8, 256); MBARRIER_INIT(MBE + 16, 256);
    }
    if (tid < 128) { num_sh[tid] = 0.f; den_sh[tid] = 0.f; }
    __syncthreads();

    const uint32_t seg = (uint32_t)(lane >> 4) * 16;
    const uint32_t aoffp0 = (uint32_t)(wm * 32 + (lane & 15)) * 128 + seg;
    const uint32_t aswz0 = SWZ(aoffp0);
    const uint32_t aswz1 = SWZ(aoffp0 + 16 * 128);
    const uint32_t bswz0 = SWZ((uint32_t)(wn * 64 + (lane & 15)) * 128 + seg);

#define QSLOT(s) (sb + 2048 + (s) * TILE_BYTES)
#define KSLOT(s) (sb + 2048 + 3*TILE_BYTES + (s) * TILE_BYTES)
#define AISSUE(gg, S) do { \
        const int _st = (gg) / NCH, _cc = (gg) % NCH; \
        MBARRIER_EXPECT_TX(MBF + 8 * (S), 2 * TILE_BYTES); \
        bulk_g2s(QSLOT(S), Qb + (((size_t)(qtile0 + _st) * NCH + _cc) << 14), \
                 TILE_BYTES, MBF + 8 * (S)); \
        bulk_g2s(KSLOT(S), Kb + (((size_t)ktile * NCH + _cc) << 14), \
                 TILE_BYTES, MBF + 8 * (S)); \
    } while (0)

#define EPI() do { \
        _Pragma("unroll") \
        for (int nt = 0; nt < 8; nt++) { \
            float vn0 = 0.f, vn1 = 0.f, vd0 = 0.f, vd1 = 0.f; \
            _Pragma("unroll") \
            for (int mt = 0; mt < 2; mt++) { \
                const float q0 = acc[mt][nt][0], q1 = acc[mt][nt][1]; \
                const float q2 = acc[mt][nt][2], q3 = acc[mt][nt][3]; \
                const float e0 = __expf(fast_tanh(q0)); \
                const float e1 = __expf(fast_tanh(q1)); \
                const float e2 = __expf(fast_tanh(q2)); \
                const float e3 = __expf(fast_tanh(q3)); \
                vn0 += e0 * q0 + e2 * q2;  vd0 += e0 + e2; \
                vn1 += e1 * q1 + e3 * q3;  vd1 += e1 + e3; \
            } \
            _Pragma("unroll") \
            for (int o = 4; o <= 16; o <<= 1) { \
                vn0 += __shfl_xor_sync(0xFFFFFFFFu, vn0, o); \
                vn1 += __shfl_xor_sync(0xFFFFFFFFu, vn1, o); \
                vd0 += __shfl_xor_sync(0xFFFFFFFFu, vd0, o); \
                vd1 += __shfl_xor_sync(0xFFFFFFFFu, vd1, o); \
            } \
            if (lane < 4) { \
                const int col = wn * 64 + nt * 8 + lane * 2; \
                atomicAdd(&num_sh[col],     vn0); \
                atomicAdd(&num_sh[col + 1], vn1); \
                atomicAdd(&den_sh[col],     vd0); \
                atomicAdd(&den_sh[col + 1], vd1); \
            } \
        } \
        _Pragma("unroll") \
        for (int i = 0; i < 2; i++) \
            _Pragma("unroll") \
            for (int j = 0; j < 8; j++) \
                _Pragma("unroll") \
                for (int q = 0; q < 4; q++) acc[i][j][q] = 0.f; \
    } while (0)

    float acc[2][8][4];
#pragma unroll
    for (int i = 0; i < 2; i++)
#pragma unroll
        for (int j = 0; j < 8; j++)
#pragma unroll
            for (int q = 0; q < 4; q++) acc[i][j][q] = 0.f;

    if (tid == 0) { AISSUE(0, 0); AISSUE(1, 1); AISSUE(2, 2); }

    int phf0 = 0, phf1 = 0, phf2 = 0;
    int phe0 = 0, phe1 = 0, phe2 = 0;

#define ABODY(gg, S, PHF, PHE, DO_EPI) do { \
        MBARRIER_WAIT_PARITY(MBF + 8 * (S), PHF); PHF ^= 1; \
        CHUNK_MMA_SW(QSLOT(S), KSLOT(S)); \
        MBARRIER_ARRIVE(MBE + 8 * (S)); \
        if (DO_EPI) EPI(); \
        if ((gg) + 3 < GTOT && tid == 0) { \
            MBARRIER_WAIT_PARITY(MBE + 8 * (S), PHE); PHE ^= 1; \
            AISSUE((gg) + 3, S); \
        } \
    } while (0)

    for (int g0 = 0; g0 < GTOT; g0 += 3) {
        ABODY(g0,     0, phf0, phe0, false);
        ABODY(g0 + 1, 1, phf1, phe1, false);
        // tiles are 12 chunks; tile-final chunk lands at slot 2 when g0%12==9
        ABODY(g0 + 2, 2, phf2, phe2, (g0 % NCH) == 9);
    }
#undef ABODY
#undef AISSUE
#undef QSLOT
#undef KSLOT
#undef EPI

    __syncthreads();
    // publish partials
    if (tid < 128) {
        atomicAdd(&gnum[(size_t)b * SEQ + t0 + tid], num_sh[tid]);
        atomicAdd(&gden[(size_t)b * SEQ + t0 + tid], den_sh[tid]);
    }
    __threadfence();   // release partials before taking a ticket
    __syncthreads();
    if (tid == 0) ticket_sh[0] = atomicAdd(&gcnt[b * 16 + blockIdx.x], 1u);
    __syncthreads();
    if (ticket_sh[0] & 1u) {
        // second CTA of the pair: both partials are visible; finalize + reset
        __threadfence();   // acquire
        if (tid < 128) {
            const size_t idx = (size_t)b * SEQ + t0 + tid;
            const float n = gnum[idx], d = gden[idx];
            out[idx] = n / (d + 1e-7f);
            gnum[idx] = 0.f;   // reset for next graph replay
            gden[idx] = 0.f;
        }
    }
}

// ---------------------------------------------------------------------------
extern "C" void kernel_launch(void* const* d_in, const int* in_sizes, int n_in,
                              void* d_out, int out_size)
{
    const float* x1 = (const float*)d_in[0];
    const float* x2 = (const float*)d_in[1];
    const float* Wq = (const float*)d_in[2];
    const float* bq = (const float*)d_in[3];
    const float* Wk = (const float*)d_in[4];
    const float* bk = (const float*)d_in[5];
    float* out = (float*)d_out;

    __nv_bfloat16 *X1b, *X2b, *Qp, *Kp, *Wqt, *Wkt;
    float *gnum, *gden;
    uint32_t* gcnt;
    cudaGetSymbolAddress((void**)&X1b, g_X1b);
    cudaGetSymbolAddress((void**)&X2b, g_X2b);
    cudaGetSymbolAddress((void**)&Qp,  g_Q);
    cudaGetSymbolAddress((void**)&Kp,  g_K);
    cudaGetSymbolAddress((void**)&Wqt, g_Wqt);
    cudaGetSymbolAddress((void**)&Wkt, g_Wkt);
    cudaGetSymbolAddress((void**)&gnum, g_num);
    cudaGetSymbolAddress((void**)&gden, g_den);
    cudaGetSymbolAddress((void**)&gcnt, g_cnt);

    cudaFuncSetAttribute(gemm_bias_mma, cudaFuncAttributeMaxDynamicSharedMemorySize, P1_SMEM);
    cudaFuncSetAttribute(attn_mma,      cudaFuncAttributeMaxDynamicSharedMemorySize, P2_SMEM);

    prep<<<dim3(NCONV + NTRANS, 1, 2), 256>>>(x1, x2, Wq, Wk, X1b, X2b, Wqt, Wkt);

    dim3 ggrid(DIM / 128, MTOT / 128, 2);   // (6, 128, 2) = 1536 CTAs
    gemm_bias_mma<<<ggrid, 256, P1_SMEM>>>(X1b, X2b, Wqt, Wkt, bq, bk, Qp, Kp);

    dim3 agrid(SEQ / 128, BATCH, 2);        // (16, 8, 2) = 256 CTAs
    attn_mma<<<agrid, 256, P2_SMEM>>>(Qp, Kp, gnum, gden, gcnt, out);
}